// round 15
// baseline (speedup 1.0000x reference)
#include <cuda_runtime.h>
#include <cuda_bf16.h>
#include <math.h>
#include <stdint.h>

// Problem constants (fixed by the reference setup)
#define NN 100000
#define EE 1600000
#define SCAN_B 1024
#define NBLK ((NN + SCAN_B - 1) / SCAN_B)   // 98

// ----------------------------------------------------------------------------
// Scratch (device globals; allocation inside kernel_launch is forbidden)
// ----------------------------------------------------------------------------
__device__ __nv_bfloat16 g_xb  [(size_t)NN * 128]; // x converted to bf16
__device__ __nv_bfloat16 g_hb  [(size_t)NN * 256]; // cell output (bf16)
__device__ __nv_bfloat16 g_hpre[(size_t)NN * 128]; // cell-1 pre-linear (bf16)
// interleaved T|S rows: [t0,t1,s0,s1,...] 256 bf16 per node
__device__ __nv_bfloat16 g_ts[(size_t)NN * 256];
// interleaved U|R rows: [u0,u1,r0,r1,...] 256 bf16 per node
__device__ __nv_bfloat16 g_ur[(size_t)NN * 256];
__device__ float  g_deg [NN];
__device__ int    g_cnti[NN];
__device__ int    g_cur [NN];
__device__ int    g_off [NN + 1];
__device__ int    g_blksum[SCAN_B];
__device__ float  g_dinv[NN];
__device__ float  g_icnt[NN];
__device__ float4 g_edge[EE];   // {src(int bits), c1, c2, pad}
// cell-0 composed weights bf16 TRANSPOSED [n][128]; biases fp32 [n]
__device__ __nv_bfloat16 g_Wt[128 * 128];
__device__ __nv_bfloat16 g_Ws[128 * 128];
__device__ __nv_bfloat16 g_Wu[128 * 128];
__device__ __nv_bfloat16 g_Wr[128 * 128];
__device__ float g_bt[128];
__device__ float g_bs[128];
__device__ float g_bu[128];
__device__ float g_br[128];
// cell-1 plain transposed weights (bf16)
__device__ __nv_bfloat16 g_Wp [128 * 256];  // pre_w1^T  [n][256]
__device__ __nv_bfloat16 g_W1t[128 * 128];  // arma_w1^T
__device__ __nv_bfloat16 g_W1s[128 * 128];  // sage_wl1^T
__device__ __nv_bfloat16 g_W1u[128 * 128];  // arma_v1^T
__device__ __nv_bfloat16 g_W1r[128 * 128];  // sage_wr1^T
__device__ float g_zero[128];               // zero-initialized, never written

// ----------------------------------------------------------------------------
// Small helpers
// ----------------------------------------------------------------------------
__device__ __forceinline__ uint32_t packbf(float a, float b) {
    __nv_bfloat162 h = __float22bfloat162_rn(make_float2(a, b));
    return *(uint32_t*)&h;
}

#define CP_ASYNC16(dst_u32, src_ptr) \
    asm volatile("cp.async.cg.shared.global [%0], [%1], 16;" \
                 :: "r"(dst_u32), "l"(src_ptr) : "memory")
#define CP_COMMIT() asm volatile("cp.async.commit_group;" ::: "memory")
#define CP_WAIT1()  asm volatile("cp.async.wait_group 1;" ::: "memory")
#define CP_WAIT0()  asm volatile("cp.async.wait_group 0;" ::: "memory")

__device__ __forceinline__ void ldsm_x4(uint32_t r[4], uint32_t saddr) {
    asm volatile("ldmatrix.sync.aligned.m8n8.x4.shared.b16 {%0,%1,%2,%3}, [%4];"
        : "=r"(r[0]), "=r"(r[1]), "=r"(r[2]), "=r"(r[3]) : "r"(saddr));
}

__device__ __forceinline__ void mma_bf16(float c[4], uint32_t a0, uint32_t a1,
                                         uint32_t a2, uint32_t a3,
                                         uint32_t b0, uint32_t b1) {
    asm volatile(
        "mma.sync.aligned.m16n8k16.row.col.f32.bf16.bf16.f32 "
        "{%0,%1,%2,%3}, {%4,%5,%6,%7}, {%8,%9}, {%0,%1,%2,%3};"
        : "+f"(c[0]), "+f"(c[1]), "+f"(c[2]), "+f"(c[3])
        : "r"(a0), "r"(a1), "r"(a2), "r"(a3), "r"(b0), "r"(b1));
}

// ----------------------------------------------------------------------------
// x -> bf16 conversion
// ----------------------------------------------------------------------------
__global__ void xcvt_kernel(const float* __restrict__ x,
                            __nv_bfloat16* __restrict__ xb, int n8) {
    int i = blockIdx.x * blockDim.x + threadIdx.x;
    if (i >= n8) return;
    const float4* p = (const float4*)(x + (size_t)i * 8);
    float4 v0 = p[0], v1 = p[1];
    uint4 u;
    u.x = packbf(v0.x, v0.y);
    u.y = packbf(v0.z, v0.w);
    u.z = packbf(v1.x, v1.y);
    u.w = packbf(v1.z, v1.w);
    *(uint4*)(xb + (size_t)i * 8) = u;
}

// ----------------------------------------------------------------------------
// Weight transpose: in fp32 [K][128] -> out bf16 [128][K]
// ----------------------------------------------------------------------------
__global__ void transpose_w_kernel(const float* __restrict__ in,
                                   __nv_bfloat16* __restrict__ out, int K) {
    int idx = blockIdx.x * blockDim.x + threadIdx.x;
    if (idx >= K * 128) return;
    int k = idx >> 7;
    int n = idx & 127;
    out[(size_t)n * K + k] = __float2bfloat16(in[idx]);
}

// ----------------------------------------------------------------------------
// CSR build
// ----------------------------------------------------------------------------
__global__ void init_counts_kernel(float* __restrict__ deg, int* __restrict__ cnt,
                                   int* __restrict__ cur, int n) {
    int i = blockIdx.x * blockDim.x + threadIdx.x;
    if (i < n) { deg[i] = 0.f; cnt[i] = 0; cur[i] = 0; }
}

__global__ void hist_kernel(const int* __restrict__ col,
                            const float* __restrict__ ew,
                            float* __restrict__ deg, int* __restrict__ cnt, int E) {
    int e = blockIdx.x * blockDim.x + threadIdx.x;
    if (e >= E) return;
    int c = col[e];
    atomicAdd(&deg[c], ew[e]);
    atomicAdd(&cnt[c], 1);
}

__global__ void dinv_kernel(const float* __restrict__ deg,
                            const int* __restrict__ cnt,
                            float* __restrict__ dinv,
                            float* __restrict__ icnt, int n) {
    int i = blockIdx.x * blockDim.x + threadIdx.x;
    if (i >= n) return;
    float d = deg[i];
    dinv[i] = (d > 0.f) ? rsqrtf(d) : 0.f;
    icnt[i] = 1.0f / fmaxf((float)cnt[i], 1.0f);
}

__global__ void scan1_kernel(const int* __restrict__ cnt, int* __restrict__ off,
                             int* __restrict__ blksum, int n) {
    __shared__ int sh[SCAN_B];
    int t = threadIdx.x;
    int i = blockIdx.x * SCAN_B + t;
    int v = (i < n) ? cnt[i] : 0;
    sh[t] = v;
    __syncthreads();
    for (int o = 1; o < SCAN_B; o <<= 1) {
        int x = (t >= o) ? sh[t - o] : 0;
        __syncthreads();
        sh[t] += x;
        __syncthreads();
    }
    if (i < n) off[i] = sh[t] - v;          // exclusive
    if (t == SCAN_B - 1) blksum[blockIdx.x] = sh[t];
}

__global__ void scan2_kernel(int* __restrict__ blksum, int nb) {
    __shared__ int sh[SCAN_B];
    int t = threadIdx.x;
    int v = (t < nb) ? blksum[t] : 0;
    sh[t] = v;
    __syncthreads();
    for (int o = 1; o < SCAN_B; o <<= 1) {
        int x = (t >= o) ? sh[t - o] : 0;
        __syncthreads();
        sh[t] += x;
        __syncthreads();
    }
    if (t < nb) blksum[t] = sh[t] - v;
}

__global__ void scan3_kernel(int* __restrict__ off, const int* __restrict__ blksum,
                             int n, int E) {
    int i = blockIdx.x * blockDim.x + threadIdx.x;
    if (i < n) off[i] += blksum[i / SCAN_B];
    if (i == 0) off[n] = E;
}

// scatter edges into CSR order as packed float4 records
__global__ void edge_sort_kernel(const int* __restrict__ row,
                                 const int* __restrict__ col,
                                 const float* __restrict__ ew,
                                 const int* __restrict__ off,
                                 int* __restrict__ cur,
                                 const float* __restrict__ dinv,
                                 const float* __restrict__ icnt,
                                 float4* __restrict__ edge, int E) {
    int e = blockIdx.x * blockDim.x + threadIdx.x;
    if (e >= E) return;
    int c = col[e];
    int r = row[e];
    float w = ew[e];
    int p = off[c] + atomicAdd(&cur[c], 1);
    float4 rec;
    rec.x = __int_as_float(r);
    rec.y = dinv[r] * w * dinv[c];
    rec.z = w * icnt[c];
    rec.w = 0.f;
    edge[p] = rec;
}

// ----------------------------------------------------------------------------
// Cell-0 weight composition, bf16 transposed: O[n][k] = sum_j pre_w[k][j]*X[j][n]
// ----------------------------------------------------------------------------
__global__ void compose_w_kernel(const float* __restrict__ pre_w, int K,
                                 const float* __restrict__ X0,
                                 const float* __restrict__ X1,
                                 const float* __restrict__ X2,
                                 const float* __restrict__ X3,
                                 __nv_bfloat16* __restrict__ O0,
                                 __nv_bfloat16* __restrict__ O1,
                                 __nv_bfloat16* __restrict__ O2,
                                 __nv_bfloat16* __restrict__ O3) {
    int idx = blockIdx.x * blockDim.x + threadIdx.x;
    if (idx >= K * 128) return;
    int k = idx >> 7;
    int n = idx & 127;
    const float* X = X0;
    __nv_bfloat16* O = O0;
    if (blockIdx.y == 1) { X = X1; O = O1; }
    else if (blockIdx.y == 2) { X = X2; O = O2; }
    else if (blockIdx.y == 3) { X = X3; O = O3; }
    float acc = 0.f;
    const float* pw = pre_w + (size_t)k * 128;
    #pragma unroll 8
    for (int j = 0; j < 128; j++)
        acc += pw[j] * __ldg(X + (size_t)j * 128 + n);
    O[(size_t)n * K + k] = __float2bfloat16(acc);
}

__global__ void compose_b_kernel(const float* __restrict__ pre_b,
                                 const float* __restrict__ X0,
                                 const float* __restrict__ X1,
                                 const float* __restrict__ X2,
                                 const float* __restrict__ X3,
                                 const float* __restrict__ e2,
                                 const float* __restrict__ e3,
                                 float* __restrict__ O0, float* __restrict__ O1,
                                 float* __restrict__ O2, float* __restrict__ O3) {
    int tid = threadIdx.x;           // 512 threads: y = tid/128, n = tid%128
    int y = tid >> 7;
    int n = tid & 127;
    const float* X = (y == 0) ? X0 : (y == 1) ? X1 : (y == 2) ? X2 : X3;
    float acc = 0.f;
    #pragma unroll 8
    for (int j = 0; j < 128; j++)
        acc += pre_b[j] * __ldg(X + (size_t)j * 128 + n);
    if (y == 2) acc += e2[n];
    if (y == 3) acc += e3[n];
    float* O = (y == 0) ? O0 : (y == 1) ? O1 : (y == 2) ? O2 : O3;
    O[n] = acc;
}

// ----------------------------------------------------------------------------
// BF16 mma.sync GEMM (m16n8k16), BK=32, cp.async double-buffered, ldmatrix.x4.
// SINGLE=0 (quad): grid (MB,4).
//   y=0: t -> TS interleaved (+0)   y=1: s -> TS interleaved (+2)
//   y=2: u -> UR interleaved (+0)   y=3: r -> UR interleaved (+2)
// SINGLE=1: one output, bf16 plain rows [gm][128] into TS.
// A bf16, row stride lda.  W bf16 [n][K].
// ----------------------------------------------------------------------------
#define ROW_U32 20          // 16 u32 data (32 bf16) + 4 pad
#define BUF_B   (128 * ROW_U32 * 4)   // 10240 bytes per tile buffer

template<int SINGLE>
__global__ __launch_bounds__(256, 2)
void quad_gemm_kernel(const __nv_bfloat16* __restrict__ A, int lda,
                      const __nv_bfloat16* __restrict__ Wt,
                      const __nv_bfloat16* __restrict__ Ws,
                      const __nv_bfloat16* __restrict__ Wu,
                      const __nv_bfloat16* __restrict__ Wr,
                      const float* __restrict__ bt, const float* __restrict__ bs,
                      const float* __restrict__ bu, const float* __restrict__ br,
                      __nv_bfloat16* __restrict__ TS,
                      __nv_bfloat16* __restrict__ UR,
                      int M, int K) {
    __shared__ uint32_t smem[2 * 2 * 128 * ROW_U32];   // 40960 bytes

    int tid = threadIdx.x;
    int lane = tid & 31;
    int wid = tid >> 5;
    int warp_m = wid & 1;
    int warp_n = wid >> 1;
    int m0 = blockIdx.x * 128;
    int y = SINGLE ? 0 : blockIdx.y;

    const __nv_bfloat16* W = (y == 0) ? Wt : (y == 1) ? Ws : (y == 2) ? Wu : Wr;
    const float* bias = (y == 0) ? bt : (y == 1) ? bs : (y == 2) ? bu : br;

    uint32_t sb = (uint32_t)__cvta_generic_to_shared(smem);

    float acc[4][4][4];
    #pragma unroll
    for (int mt = 0; mt < 4; mt++)
        #pragma unroll
        for (int nt = 0; nt < 4; nt++)
            #pragma unroll
            for (int q = 0; q < 4; q++) acc[mt][nt][q] = 0.f;

    int arow = (lane & 7) + (((lane >> 3) & 1) << 3);
    int acol = (((lane >> 4) & 1) << 4);
    int brow = (lane & 7) + (((lane >> 4) & 1) << 3);
    int bcol = (((lane >> 3) & 1) << 4);

    int srow = tid >> 2;
    int sc4  = tid & 3;

    int nch = K >> 5;

    // prologue: stage chunk 0 into buffers 0
    {
        #pragma unroll
        for (int it = 0; it < 2; it++) {
            int r0 = srow + it * 64;
            int gm = m0 + r0;
            uint32_t dA = sb + (uint32_t)(r0 * 80 + sc4 * 16);
            if (gm < M) {
                CP_ASYNC16(dA, A + (size_t)gm * lda + sc4 * 8);
            } else {
                *(uint4*)((char*)smem + r0 * 80 + sc4 * 16) = make_uint4(0, 0, 0, 0);
            }
            uint32_t dB = sb + (uint32_t)(BUF_B + r0 * 80 + sc4 * 16);
            CP_ASYNC16(dB, W + (size_t)r0 * K + sc4 * 8);
        }
        CP_COMMIT();
    }

    for (int c = 0; c < nch; c++) {
        if (c + 1 < nch) {
            int st = (c + 1) & 1;
            int k0 = (c + 1) << 5;
            char* base = (char*)smem + st * 2 * BUF_B;
            uint32_t sbase = sb + (uint32_t)(st * 2 * BUF_B);
            #pragma unroll
            for (int it = 0; it < 2; it++) {
                int r0 = srow + it * 64;
                int gm = m0 + r0;
                uint32_t dA = sbase + (uint32_t)(r0 * 80 + sc4 * 16);
                if (gm < M) {
                    CP_ASYNC16(dA, A + (size_t)gm * lda + k0 + sc4 * 8);
                } else {
                    *(uint4*)(base + r0 * 80 + sc4 * 16) = make_uint4(0, 0, 0, 0);
                }
                uint32_t dB = sbase + (uint32_t)(BUF_B + r0 * 80 + sc4 * 16);
                CP_ASYNC16(dB, W + (size_t)r0 * K + k0 + sc4 * 8);
            }
            CP_COMMIT();
            CP_WAIT1();
        } else {
            CP_WAIT0();
        }
        __syncthreads();

        uint32_t baseA = sb + (uint32_t)((c & 1) * 2 * BUF_B);
        uint32_t baseB = baseA + BUF_B;
        #pragma unroll
        for (int s = 0; s < 2; s++) {
            uint32_t af[4][4];
            #pragma unroll
            for (int mt = 0; mt < 4; mt++)
                ldsm_x4(af[mt], baseA + (uint32_t)((warp_m * 64 + mt * 16 + arow) * 80
                                                   + s * 32 + acol));
            uint32_t bfr[2][4];
            #pragma unroll
            for (int p = 0; p < 2; p++)
                ldsm_x4(bfr[p], baseB + (uint32_t)((warp_n * 32 + p * 16 + brow) * 80
                                                   + s * 32 + bcol));
            #pragma unroll
            for (int nt = 0; nt < 4; nt++) {
                uint32_t b0 = bfr[nt >> 1][(nt & 1) * 2 + 0];
                uint32_t b1 = bfr[nt >> 1][(nt & 1) * 2 + 1];
                #pragma unroll
                for (int mt = 0; mt < 4; mt++)
                    mma_bf16(acc[mt][nt], af[mt][0], af[mt][1], af[mt][2], af[mt][3],
                             b0, b1);
            }
        }
        __syncthreads();
    }

    // ---- epilogue ----
    int lr = lane >> 2;
    int lc = lane & 3;
    #pragma unroll
    for (int nt = 0; nt < 4; nt++) {
        int n = warp_n * 32 + nt * 8 + lc * 2;
        float2 bv = __ldg((const float2*)(bias + n));
        #pragma unroll
        for (int mt = 0; mt < 4; mt++) {
            #pragma unroll
            for (int h = 0; h < 2; h++) {
                int gm = m0 + warp_m * 64 + mt * 16 + lr + h * 8;
                if (gm >= M) continue;
                float v0 = acc[mt][nt][h * 2 + 0] + bv.x;
                float v1 = acc[mt][nt][h * 2 + 1] + bv.y;
                __nv_bfloat162 o = __float22bfloat162_rn(make_float2(v0, v1));
                if (SINGLE) {
                    *(__nv_bfloat162*)(TS + (size_t)gm * 128 + n) = o;
                } else {
                    __nv_bfloat16* P = (y < 2) ? TS : UR;
                    *(__nv_bfloat162*)(P + (size_t)gm * 256 + 2 * n + ((y & 1) ? 2 : 0)) = o;
                }
            }
        }
    }
}

// ----------------------------------------------------------------------------
// Fused aggregation + cell epilogue: warp per destination node.
// Packed 16B edge records (ONE uniform LDG.128) + interleaved TS gathers
// (ONE uint4 per edge per lane) + interleaved bf16 UR epilogue read.
//   h[:,0:128]   = relu(agg1 + u)         (bf16 out)
//   h[:,128:256] = elu(leaky(agg2 + r))   (bf16 out)
// ----------------------------------------------------------------------------
__global__ __launch_bounds__(256)
void agg_epi_kernel(const int* __restrict__ off,
                    const float4* __restrict__ edge,
                    const __nv_bfloat16* __restrict__ TS,
                    const __nv_bfloat16* __restrict__ UR,
                    __nv_bfloat16* __restrict__ H, int N) {
    int lane = threadIdx.x & 31;
    int w = (blockIdx.x * blockDim.x + threadIdx.x) >> 5;
    if (w >= N) return;
    int s0 = __ldg(off + w);
    int s1 = __ldg(off + w + 1);
    float a1x = 0.f, a1y = 0.f, a1z = 0.f, a1w = 0.f;
    float a2x = 0.f, a2y = 0.f, a2z = 0.f, a2w = 0.f;
    #pragma unroll 2
    for (int e = s0; e < s1; e++) {
        float4 rec = __ldg(edge + e);
        int sr = __float_as_int(rec.x);
        uint4 v = __ldg((const uint4*)(TS + (size_t)sr * 256) + lane);
        float2 t0 = __bfloat1622float2(*(__nv_bfloat162*)&v.x);
        float2 q0 = __bfloat1622float2(*(__nv_bfloat162*)&v.y);
        float2 t1 = __bfloat1622float2(*(__nv_bfloat162*)&v.z);
        float2 q1 = __bfloat1622float2(*(__nv_bfloat162*)&v.w);
        float c1 = rec.y, c2 = rec.z;
        a1x += c1 * t0.x; a1y += c1 * t0.y; a1z += c1 * t1.x; a1w += c1 * t1.y;
        a2x += c2 * q0.x; a2y += c2 * q0.y; a2z += c2 * q1.x; a2w += c2 * q1.y;
    }
    // epilogue: one uint4 read of interleaved u/r
    uint4 urv = __ldg((const uint4*)(UR + (size_t)w * 256) + lane);
    float2 u0 = __bfloat1622float2(*(__nv_bfloat162*)&urv.x);
    float2 r0 = __bfloat1622float2(*(__nv_bfloat162*)&urv.y);
    float2 u1 = __bfloat1622float2(*(__nv_bfloat162*)&urv.z);
    float2 r1 = __bfloat1622float2(*(__nv_bfloat162*)&urv.w);

    float h1x = fmaxf(a1x + u0.x, 0.f);
    float h1y = fmaxf(a1y + u0.y, 0.f);
    float h1z = fmaxf(a1z + u1.x, 0.f);
    float h1w = fmaxf(a1w + u1.y, 0.f);
    float v, h2x, h2y, h2z, h2w;
    v = a2x + r0.x; h2x = (v > 0.f) ? v : expm1f(0.01f * v);
    v = a2y + r0.y; h2y = (v > 0.f) ? v : expm1f(0.01f * v);
    v = a2z + r1.x; h2z = (v > 0.f) ? v : expm1f(0.01f * v);
    v = a2w + r1.y; h2w = (v > 0.f) ? v : expm1f(0.01f * v);

    uint2 o1, o2;
    *(__nv_bfloat162*)&o1.x = __float22bfloat162_rn(make_float2(h1x, h1y));
    *(__nv_bfloat162*)&o1.y = __float22bfloat162_rn(make_float2(h1z, h1w));
    *(__nv_bfloat162*)&o2.x = __float22bfloat162_rn(make_float2(h2x, h2y));
    *(__nv_bfloat162*)&o2.y = __float22bfloat162_rn(make_float2(h2z, h2w));
    *(uint2*)(H + (size_t)w * 256 + lane * 4) = o1;
    *(uint2*)(H + (size_t)w * 256 + 128 + lane * 4) = o2;
}

// ----------------------------------------------------------------------------
// Classifier (bf16 input): logits = h @ cls_w + cls_b ; out = log_softmax
// ----------------------------------------------------------------------------
__global__ __launch_bounds__(256)
void cls_kernel(const __nv_bfloat16* __restrict__ h, const float* __restrict__ W,
                const float* __restrict__ b, float* __restrict__ out, int M) {
    __shared__ float WsT[16 * 256];
    __shared__ float Bsm[16];
    int tid = threadIdx.x;
    for (int idx = tid; idx < 16 * 256; idx += 256) {
        int c = idx >> 8, k = idx & 255;
        WsT[c * 256 + k] = W[k * 16 + c];
    }
    if (tid < 16) Bsm[tid] = b[tid];
    __syncthreads();

    int warp = tid >> 5;
    int lane = tid & 31;
    for (int n = blockIdx.x * 8 + warp; n < M; n += gridDim.x * 8) {
        uint4 raw = __ldg((const uint4*)(h + (size_t)n * 256 + lane * 8));
        float hv[8];
        {
            float2 f0 = __bfloat1622float2(*(__nv_bfloat162*)&raw.x);
            float2 f1 = __bfloat1622float2(*(__nv_bfloat162*)&raw.y);
            float2 f2 = __bfloat1622float2(*(__nv_bfloat162*)&raw.z);
            float2 f3 = __bfloat1622float2(*(__nv_bfloat162*)&raw.w);
            hv[0] = f0.x; hv[1] = f0.y; hv[2] = f1.x; hv[3] = f1.y;
            hv[4] = f2.x; hv[5] = f2.y; hv[6] = f3.x; hv[7] = f3.y;
        }
        float acc[16];
        #pragma unroll
        for (int c = 0; c < 16; c++) {
            const float4* wp = (const float4*)&WsT[c * 256 + lane * 8];
            float4 w0 = wp[0];
            float4 w1 = wp[1];
            acc[c] = hv[0] * w0.x + hv[1] * w0.y + hv[2] * w0.z + hv[3] * w0.w
                   + hv[4] * w1.x + hv[5] * w1.y + hv[6] * w1.z + hv[7] * w1.w;
        }
        #pragma unroll
        for (int c = 0; c < 16; c++) {
            #pragma unroll
            for (int offs = 16; offs > 0; offs >>= 1)
                acc[c] += __shfl_xor_sync(0xFFFFFFFFu, acc[c], offs);
        }
        float l[16];
        float mx = -3.402823e38f;
        #pragma unroll
        for (int c = 0; c < 16; c++) { l[c] = acc[c] + Bsm[c]; mx = fmaxf(mx, l[c]); }
        float se = 0.f;
        #pragma unroll
        for (int c = 0; c < 16; c++) se += expf(l[c] - mx);
        float lse = mx + logf(se);
        if (lane < 16) out[(size_t)n * 16 + lane] = l[lane] - lse;
    }
}

// ----------------------------------------------------------------------------
// Launch — multi-stream capture (R12 structure; static stream/events so the
// lazy channel allocation happens on the uncaptured first call).
// ----------------------------------------------------------------------------
static void* sym(const void* s) {
    void* p = nullptr;
    cudaGetSymbolAddress(&p, s);
    return p;
}

extern "C" void kernel_launch(void* const* d_in, const int* in_sizes, int n_in,
                              void* d_out, int out_size) {
    const float* x        = (const float*)d_in[0];
    const int*   ei       = (const int*)  d_in[1];
    const float* ew       = (const float*)d_in[2];
    const float* pre_w0   = (const float*)d_in[3];
    const float* pre_b0   = (const float*)d_in[4];
    const float* arma_w0  = (const float*)d_in[5];
    const float* arma_v0  = (const float*)d_in[6];
    const float* arma_b0  = (const float*)d_in[7];
    const float* sage_wl0 = (const float*)d_in[8];
    const float* sage_bl0 = (const float*)d_in[9];
    const float* sage_wr0 = (const float*)d_in[10];
    const float* pre_w1   = (const float*)d_in[11];
    const float* pre_b1   = (const float*)d_in[12];
    const float* arma_w1  = (const float*)d_in[13];
    const float* arma_v1  = (const float*)d_in[14];
    const float* arma_b1  = (const float*)d_in[15];
    const float* sage_wl1 = (const float*)d_in[16];
    const float* sage_bl1 = (const float*)d_in[17];
    const float* sage_wr1 = (const float*)d_in[18];
    const float* cls_w    = (const float*)d_in[19];
    const float* cls_b    = (const float*)d_in[20];
    float* out = (float*)d_out;

    const int* row = ei;
    const int* col = ei + EE;

    __nv_bfloat16* pxb   = (__nv_bfloat16*)sym(g_xb);
    __nv_bfloat16* phb   = (__nv_bfloat16*)sym(g_hb);
    __nv_bfloat16* phpre = (__nv_bfloat16*)sym(g_hpre);
    __nv_bfloat16* pts = (__nv_bfloat16*)sym(g_ts);
    __nv_bfloat16* pur = (__nv_bfloat16*)sym(g_ur);
    float*  pdeg  = (float*) sym(g_deg);
    int*    pcnti = (int*)   sym(g_cnti);
    int*    pcur  = (int*)   sym(g_cur);
    int*    poff  = (int*)   sym(g_off);
    int*    pblk  = (int*)   sym(g_blksum);
    float*  pdinv = (float*) sym(g_dinv);
    float*  picnt = (float*) sym(g_icnt);
    float4* pedge = (float4*)sym(g_edge);
    __nv_bfloat16* pWt = (__nv_bfloat16*)sym(g_Wt);
    __nv_bfloat16* pWs = (__nv_bfloat16*)sym(g_Ws);
    __nv_bfloat16* pWu = (__nv_bfloat16*)sym(g_Wu);
    __nv_bfloat16* pWr = (__nv_bfloat16*)sym(g_Wr);
    float* pbt = (float*)sym(g_bt); float* pbs = (float*)sym(g_bs);
    float* pbu = (float*)sym(g_bu); float* pbr = (float*)sym(g_br);
    __nv_bfloat16* pWp  = (__nv_bfloat16*)sym(g_Wp);
    __nv_bfloat16* pW1t = (__nv_bfloat16*)sym(g_W1t);
    __nv_bfloat16* pW1s = (__nv_bfloat16*)sym(g_W1s);
    __nv_bfloat16* pW1u = (__nv_bfloat16*)sym(g_W1u);
    __nv_bfloat16* pW1r = (__nv_bfloat16*)sym(g_W1r);
    float* pzero = (float*)sym(g_zero);

    const int M = NN;
    const int MB = (M + 127) / 128;
    const int agg_blocks = (NN * 32 + 255) / 256;
    const int n8 = NN * 128 / 8;

    // One-time stream/event creation (first call = uncaptured correctness run)
    struct Ctx {
        cudaStream_t s2;
        cudaEvent_t eFork, eCsr, eW1;
        Ctx() {
            cudaStreamCreateWithFlags(&s2, cudaStreamNonBlocking);
            cudaEventCreateWithFlags(&eFork, cudaEventDisableTiming);
            cudaEventCreateWithFlags(&eCsr,  cudaEventDisableTiming);
            cudaEventCreateWithFlags(&eW1,   cudaEventDisableTiming);
        }
    };
    static Ctx ctx;
    cudaStream_t s2 = ctx.s2;

    cudaEventRecord(ctx.eFork, 0);

    // ---- main stream: cell-0 compose + x conversion + quad GEMM ----
    compose_w_kernel<<<dim3(128 * 128 / 256, 4), 256>>>(        // idx 0
        pre_w0, 128, arma_w0, sage_wl0, arma_v0, sage_wr0, pWt, pWs, pWu, pWr);
    compose_b_kernel<<<1, 512>>>(pre_b0, arma_w0, sage_wl0,     // idx 1
                                 arma_v0, sage_wr0, arma_b0, sage_bl0,
                                 pbt, pbs, pbu, pbr);
    xcvt_kernel<<<(n8 + 255) / 256, 256>>>(x, pxb, n8);         // idx 2
    quad_gemm_kernel<0><<<dim3(MB, 4), 256>>>(                  // idx 3 <- profiled
        pxb, 128, pWt, pWs, pWu, pWr, pbt, pbs, pbu, pbr,
        pts, pur, M, 128);

    // ---- side stream: cell-1 weight transposes, then CSR build ----
    cudaStreamWaitEvent(s2, ctx.eFork, 0);
    transpose_w_kernel<<<(256 * 128 + 255) / 256, 256, 0, s2>>>(pre_w1, pWp, 256);
    transpose_w_kernel<<<(128 * 128 + 255) / 256, 256, 0, s2>>>(arma_w1, pW1t, 128);
    transpose_w_kernel<<<(128 * 128 + 255) / 256, 256, 0, s2>>>(sage_wl1, pW1s, 128);
    transpose_w_kernel<<<(128 * 128 + 255) / 256, 256, 0, s2>>>(arma_v1, pW1u, 128);
    transpose_w_kernel<<<(128 * 128 + 255) / 256, 256, 0, s2>>>(sage_wr1, pW1r, 128);
    cudaEventRecord(ctx.eW1, s2);
    init_counts_kernel<<<(NN + 255) / 256, 256, 0, s2>>>(pdeg, pcnti, pcur, NN);
    hist_kernel<<<(EE + 255) / 256, 256, 0, s2>>>(col, ew, pdeg, pcnti, EE);
    dinv_kernel<<<(NN + 255) / 256, 256, 0, s2>>>(pdeg, pcnti, pdinv, picnt, NN);
    scan1_kernel<<<NBLK, SCAN_B, 0, s2>>>(pcnti, poff, pblk, NN);
    scan2_kernel<<<1, SCAN_B, 0, s2>>>(pblk, NBLK);
    scan3_kernel<<<(NN + 255) / 256, 256, 0, s2>>>(poff, pblk, NN, EE);
    edge_sort_kernel<<<(EE + 255) / 256, 256, 0, s2>>>(row, col, ew, poff, pcur,
                                                       pdinv, picnt, pedge, EE);
    cudaEventRecord(ctx.eCsr, s2);

    // ---- main stream: cell 0 aggregation (needs CSR + gemm0) ----
    cudaStreamWaitEvent(0, ctx.eCsr, 0);
    agg_epi_kernel<<<agg_blocks, 256>>>(poff, pedge, pts, pur, phb, NN);

    // ---- main stream: cell 1, two-stage ----
    cudaStreamWaitEvent(0, ctx.eW1, 0);
    // hpre = h @ pre_w1 + pre_b1  (K=256, single bf16 output)
    quad_gemm_kernel<1><<<dim3(MB, 1), 256>>>(
        phb, 256, pWp, nullptr, nullptr, nullptr,
        pre_b1, nullptr, nullptr, nullptr,
        phpre, nullptr, M, 256);
    // t,s,u,r from hpre (K=128, plain transposed weights, pass-through biases)
    quad_gemm_kernel<0><<<dim3(MB, 4), 256>>>(
        phpre, 128, pW1t, pW1s, pW1u, pW1r,
        pzero, pzero, arma_b1, sage_bl1,
        pts, pur, M, 128);
    agg_epi_kernel<<<agg_blocks, 256>>>(poff, pedge, pts, pur, phb, NN);

    // ---- classifier + log_softmax ----
    cls_kernel<<<(M + 7) / 8, 256>>>(phb, cls_w, cls_b, out, M);
}

// round 16
// speedup vs baseline: 1.0616x; 1.0616x over previous
#include <cuda_runtime.h>
#include <cuda_bf16.h>
#include <math.h>
#include <stdint.h>

// Problem constants (fixed by the reference setup)
#define NN 100000
#define EE 1600000
#define SCAN_B 1024
#define NBLK ((NN + SCAN_B - 1) / SCAN_B)   // 98
#define H1N 50048                            // 391 * 128 (first half, block-aligned)
#define H2N (NN - H1N)                       // 49952

// ----------------------------------------------------------------------------
// Scratch (device globals; allocation inside kernel_launch is forbidden)
// ----------------------------------------------------------------------------
__device__ __nv_bfloat16 g_xb  [(size_t)NN * 128]; // x converted to bf16
__device__ __nv_bfloat16 g_hb  [(size_t)NN * 256]; // cell output (bf16)
__device__ __nv_bfloat16 g_hpre[(size_t)NN * 128]; // cell-1 pre-linear (bf16)
__device__ float g_u [(size_t)NN * 128];
__device__ float g_r [(size_t)NN * 128];
// interleaved T|S rows: [t0,t1,s0,s1,...] 256 bf16 per node
__device__ __nv_bfloat16 g_ts[(size_t)NN * 256];
__device__ float  g_deg [NN];
__device__ int    g_cnti[NN];
__device__ int    g_cur [NN];
__device__ int    g_off [NN + 1];
__device__ int    g_blksum[SCAN_B];
__device__ float  g_dinv[NN];
__device__ float  g_icnt[NN];
__device__ int    g_ssrc[EE];
__device__ float2 g_scoef[EE];
// cell-0 composed weights bf16 TRANSPOSED [n][128]; biases fp32 [n]
__device__ __nv_bfloat16 g_Wt[128 * 128];
__device__ __nv_bfloat16 g_Ws[128 * 128];
__device__ __nv_bfloat16 g_Wu[128 * 128];
__device__ __nv_bfloat16 g_Wr[128 * 128];
__device__ float g_bt[128];
__device__ float g_bs[128];
__device__ float g_bu[128];
__device__ float g_br[128];
// cell-1 plain transposed weights (bf16)
__device__ __nv_bfloat16 g_Wp [128 * 256];  // pre_w1^T  [n][256]
__device__ __nv_bfloat16 g_W1t[128 * 128];  // arma_w1^T
__device__ __nv_bfloat16 g_W1s[128 * 128];  // sage_wl1^T
__device__ __nv_bfloat16 g_W1u[128 * 128];  // arma_v1^T
__device__ __nv_bfloat16 g_W1r[128 * 128];  // sage_wr1^T
__device__ float g_zero[128];               // zero-initialized, never written

// ----------------------------------------------------------------------------
// Small helpers
// ----------------------------------------------------------------------------
__device__ __forceinline__ uint32_t packbf(float a, float b) {
    __nv_bfloat162 h = __float22bfloat162_rn(make_float2(a, b));
    return *(uint32_t*)&h;
}

#define CP_ASYNC16(dst_u32, src_ptr) \
    asm volatile("cp.async.cg.shared.global [%0], [%1], 16;" \
                 :: "r"(dst_u32), "l"(src_ptr) : "memory")
#define CP_COMMIT() asm volatile("cp.async.commit_group;" ::: "memory")
#define CP_WAIT1()  asm volatile("cp.async.wait_group 1;" ::: "memory")
#define CP_WAIT0()  asm volatile("cp.async.wait_group 0;" ::: "memory")

__device__ __forceinline__ void ldsm_x4(uint32_t r[4], uint32_t saddr) {
    asm volatile("ldmatrix.sync.aligned.m8n8.x4.shared.b16 {%0,%1,%2,%3}, [%4];"
        : "=r"(r[0]), "=r"(r[1]), "=r"(r[2]), "=r"(r[3]) : "r"(saddr));
}

__device__ __forceinline__ void mma_bf16(float c[4], uint32_t a0, uint32_t a1,
                                         uint32_t a2, uint32_t a3,
                                         uint32_t b0, uint32_t b1) {
    asm volatile(
        "mma.sync.aligned.m16n8k16.row.col.f32.bf16.bf16.f32 "
        "{%0,%1,%2,%3}, {%4,%5,%6,%7}, {%8,%9}, {%0,%1,%2,%3};"
        : "+f"(c[0]), "+f"(c[1]), "+f"(c[2]), "+f"(c[3])
        : "r"(a0), "r"(a1), "r"(a2), "r"(a3), "r"(b0), "r"(b1));
}

// ----------------------------------------------------------------------------
// x -> bf16 conversion
// ----------------------------------------------------------------------------
__global__ void xcvt_kernel(const float* __restrict__ x,
                            __nv_bfloat16* __restrict__ xb, int n8) {
    int i = blockIdx.x * blockDim.x + threadIdx.x;
    if (i >= n8) return;
    const float4* p = (const float4*)(x + (size_t)i * 8);
    float4 v0 = p[0], v1 = p[1];
    uint4 u;
    u.x = packbf(v0.x, v0.y);
    u.y = packbf(v0.z, v0.w);
    u.z = packbf(v1.x, v1.y);
    u.w = packbf(v1.z, v1.w);
    *(uint4*)(xb + (size_t)i * 8) = u;
}

// ----------------------------------------------------------------------------
// Weight transpose: in fp32 [K][128] -> out bf16 [128][K]
// ----------------------------------------------------------------------------
__global__ void transpose_w_kernel(const float* __restrict__ in,
                                   __nv_bfloat16* __restrict__ out, int K) {
    int idx = blockIdx.x * blockDim.x + threadIdx.x;
    if (idx >= K * 128) return;
    int k = idx >> 7;
    int n = idx & 127;
    out[(size_t)n * K + k] = __float2bfloat16(in[idx]);
}

// ----------------------------------------------------------------------------
// CSR build
// ----------------------------------------------------------------------------
__global__ void init_counts_kernel(float* __restrict__ deg, int* __restrict__ cnt,
                                   int* __restrict__ cur, int n) {
    int i = blockIdx.x * blockDim.x + threadIdx.x;
    if (i < n) { deg[i] = 0.f; cnt[i] = 0; cur[i] = 0; }
}

__global__ void hist_kernel(const int* __restrict__ col,
                            const float* __restrict__ ew,
                            float* __restrict__ deg, int* __restrict__ cnt, int E) {
    int e = blockIdx.x * blockDim.x + threadIdx.x;
    if (e >= E) return;
    int c = col[e];
    atomicAdd(&deg[c], ew[e]);
    atomicAdd(&cnt[c], 1);
}

__global__ void dinv_kernel(const float* __restrict__ deg,
                            const int* __restrict__ cnt,
                            float* __restrict__ dinv,
                            float* __restrict__ icnt, int n) {
    int i = blockIdx.x * blockDim.x + threadIdx.x;
    if (i >= n) return;
    float d = deg[i];
    dinv[i] = (d > 0.f) ? rsqrtf(d) : 0.f;
    icnt[i] = 1.0f / fmaxf((float)cnt[i], 1.0f);
}

__global__ void scan1_kernel(const int* __restrict__ cnt, int* __restrict__ off,
                             int* __restrict__ blksum, int n) {
    __shared__ int sh[SCAN_B];
    int t = threadIdx.x;
    int i = blockIdx.x * SCAN_B + t;
    int v = (i < n) ? cnt[i] : 0;
    sh[t] = v;
    __syncthreads();
    for (int o = 1; o < SCAN_B; o <<= 1) {
        int x = (t >= o) ? sh[t - o] : 0;
        __syncthreads();
        sh[t] += x;
        __syncthreads();
    }
    if (i < n) off[i] = sh[t] - v;          // exclusive
    if (t == SCAN_B - 1) blksum[blockIdx.x] = sh[t];
}

__global__ void scan2_kernel(int* __restrict__ blksum, int nb) {
    __shared__ int sh[SCAN_B];
    int t = threadIdx.x;
    int v = (t < nb) ? blksum[t] : 0;
    sh[t] = v;
    __syncthreads();
    for (int o = 1; o < SCAN_B; o <<= 1) {
        int x = (t >= o) ? sh[t - o] : 0;
        __syncthreads();
        sh[t] += x;
        __syncthreads();
    }
    if (t < nb) blksum[t] = sh[t] - v;
}

__global__ void scan3_kernel(int* __restrict__ off, const int* __restrict__ blksum,
                             int n, int E) {
    int i = blockIdx.x * blockDim.x + threadIdx.x;
    if (i < n) off[i] += blksum[i / SCAN_B];
    if (i == 0) off[n] = E;
}

__global__ void edge_sort_kernel(const int* __restrict__ row,
                                 const int* __restrict__ col,
                                 const float* __restrict__ ew,
                                 const int* __restrict__ off,
                                 int* __restrict__ cur,
                                 const float* __restrict__ dinv,
                                 const float* __restrict__ icnt,
                                 int* __restrict__ ssrc,
                                 float2* __restrict__ scoef, int E) {
    int e = blockIdx.x * blockDim.x + threadIdx.x;
    if (e >= E) return;
    int c = col[e];
    int r = row[e];
    float w = ew[e];
    int p = off[c] + atomicAdd(&cur[c], 1);
    ssrc[p] = r;
    scoef[p] = make_float2(dinv[r] * w * dinv[c], w * icnt[c]);
}

// ----------------------------------------------------------------------------
// Cell-0 weight composition, bf16 transposed: O[n][k] = sum_j pre_w[k][j]*X[j][n]
// ----------------------------------------------------------------------------
__global__ void compose_w_kernel(const float* __restrict__ pre_w, int K,
                                 const float* __restrict__ X0,
                                 const float* __restrict__ X1,
                                 const float* __restrict__ X2,
                                 const float* __restrict__ X3,
                                 __nv_bfloat16* __restrict__ O0,
                                 __nv_bfloat16* __restrict__ O1,
                                 __nv_bfloat16* __restrict__ O2,
                                 __nv_bfloat16* __restrict__ O3) {
    int idx = blockIdx.x * blockDim.x + threadIdx.x;
    if (idx >= K * 128) return;
    int k = idx >> 7;
    int n = idx & 127;
    const float* X = X0;
    __nv_bfloat16* O = O0;
    if (blockIdx.y == 1) { X = X1; O = O1; }
    else if (blockIdx.y == 2) { X = X2; O = O2; }
    else if (blockIdx.y == 3) { X = X3; O = O3; }
    float acc = 0.f;
    const float* pw = pre_w + (size_t)k * 128;
    #pragma unroll 8
    for (int j = 0; j < 128; j++)
        acc += pw[j] * __ldg(X + (size_t)j * 128 + n);
    O[(size_t)n * K + k] = __float2bfloat16(acc);
}

__global__ void compose_b_kernel(const float* __restrict__ pre_b,
                                 const float* __restrict__ X0,
                                 const float* __restrict__ X1,
                                 const float* __restrict__ X2,
                                 const float* __restrict__ X3,
                                 const float* __restrict__ e2,
                                 const float* __restrict__ e3,
                                 float* __restrict__ O0, float* __restrict__ O1,
                                 float* __restrict__ O2, float* __restrict__ O3) {
    int tid = threadIdx.x;           // 512 threads: y = tid/128, n = tid%128
    int y = tid >> 7;
    int n = tid & 127;
    const float* X = (y == 0) ? X0 : (y == 1) ? X1 : (y == 2) ? X2 : X3;
    float acc = 0.f;
    #pragma unroll 8
    for (int j = 0; j < 128; j++)
        acc += pre_b[j] * __ldg(X + (size_t)j * 128 + n);
    if (y == 2) acc += e2[n];
    if (y == 3) acc += e3[n];
    float* O = (y == 0) ? O0 : (y == 1) ? O1 : (y == 2) ? O2 : O3;
    O[n] = acc;
}

// ----------------------------------------------------------------------------
// BF16 mma.sync GEMM (m16n8k16), BK=32, cp.async double-buffered, ldmatrix.x4.
// SINGLE=0 (quad): grid (MB,4). y=0: t -> TS interleaved; y=1: s -> TS
//   interleaved (+2 bf16 offset); y=2: U fp32; y=3: R fp32.
// SINGLE=1: one output, bf16 plain rows [gm][128] into TS.
// A bf16, row stride lda.  W bf16 [n][K].
// All pointers may be pre-offset by a node-range base; M is the range size.
// ----------------------------------------------------------------------------
#define ROW_U32 20          // 16 u32 data (32 bf16) + 4 pad
#define BUF_B   (128 * ROW_U32 * 4)   // 10240 bytes per tile buffer

template<int SINGLE>
__global__ __launch_bounds__(256, 2)
void quad_gemm_kernel(const __nv_bfloat16* __restrict__ A, int lda,
                      const __nv_bfloat16* __restrict__ Wt,
                      const __nv_bfloat16* __restrict__ Ws,
                      const __nv_bfloat16* __restrict__ Wu,
                      const __nv_bfloat16* __restrict__ Wr,
                      const float* __restrict__ bt, const float* __restrict__ bs,
                      const float* __restrict__ bu, const float* __restrict__ br,
                      __nv_bfloat16* __restrict__ TS,
                      float* __restrict__ U, float* __restrict__ R,
                      int M, int K) {
    __shared__ uint32_t smem[2 * 2 * 128 * ROW_U32];   // 40960 bytes

    int tid = threadIdx.x;
    int lane = tid & 31;
    int wid = tid >> 5;
    int warp_m = wid & 1;
    int warp_n = wid >> 1;
    int m0 = blockIdx.x * 128;
    int y = SINGLE ? 0 : blockIdx.y;

    const __nv_bfloat16* W = (y == 0) ? Wt : (y == 1) ? Ws : (y == 2) ? Wu : Wr;
    const float* bias = (y == 0) ? bt : (y == 1) ? bs : (y == 2) ? bu : br;

    uint32_t sb = (uint32_t)__cvta_generic_to_shared(smem);

    float acc[4][4][4];
    #pragma unroll
    for (int mt = 0; mt < 4; mt++)
        #pragma unroll
        for (int nt = 0; nt < 4; nt++)
            #pragma unroll
            for (int q = 0; q < 4; q++) acc[mt][nt][q] = 0.f;

    int arow = (lane & 7) + (((lane >> 3) & 1) << 3);
    int acol = (((lane >> 4) & 1) << 4);
    int brow = (lane & 7) + (((lane >> 4) & 1) << 3);
    int bcol = (((lane >> 3) & 1) << 4);

    int srow = tid >> 2;
    int sc4  = tid & 3;

    int nch = K >> 5;

    // prologue: stage chunk 0 into buffers 0
    {
        #pragma unroll
        for (int it = 0; it < 2; it++) {
            int r0 = srow + it * 64;
            int gm = m0 + r0;
            uint32_t dA = sb + (uint32_t)(r0 * 80 + sc4 * 16);
            if (gm < M) {
                CP_ASYNC16(dA, A + (size_t)gm * lda + sc4 * 8);
            } else {
                *(uint4*)((char*)smem + r0 * 80 + sc4 * 16) = make_uint4(0, 0, 0, 0);
            }
            uint32_t dB = sb + (uint32_t)(BUF_B + r0 * 80 + sc4 * 16);
            CP_ASYNC16(dB, W + (size_t)r0 * K + sc4 * 8);
        }
        CP_COMMIT();
    }

    for (int c = 0; c < nch; c++) {
        if (c + 1 < nch) {
            int st = (c + 1) & 1;
            int k0 = (c + 1) << 5;
            char* base = (char*)smem + st * 2 * BUF_B;
            uint32_t sbase = sb + (uint32_t)(st * 2 * BUF_B);
            #pragma unroll
            for (int it = 0; it < 2; it++) {
                int r0 = srow + it * 64;
                int gm = m0 + r0;
                uint32_t dA = sbase + (uint32_t)(r0 * 80 + sc4 * 16);
                if (gm < M) {
                    CP_ASYNC16(dA, A + (size_t)gm * lda + k0 + sc4 * 8);
                } else {
                    *(uint4*)(base + r0 * 80 + sc4 * 16) = make_uint4(0, 0, 0, 0);
                }
                uint32_t dB = sbase + (uint32_t)(BUF_B + r0 * 80 + sc4 * 16);
                CP_ASYNC16(dB, W + (size_t)r0 * K + k0 + sc4 * 8);
            }
            CP_COMMIT();
            CP_WAIT1();
        } else {
            CP_WAIT0();
        }
        __syncthreads();

        uint32_t baseA = sb + (uint32_t)((c & 1) * 2 * BUF_B);
        uint32_t baseB = baseA + BUF_B;
        #pragma unroll
        for (int s = 0; s < 2; s++) {
            uint32_t af[4][4];
            #pragma unroll
            for (int mt = 0; mt < 4; mt++)
                ldsm_x4(af[mt], baseA + (uint32_t)((warp_m * 64 + mt * 16 + arow) * 80
                                                   + s * 32 + acol));
            uint32_t bfr[2][4];
            #pragma unroll
            for (int p = 0; p < 2; p++)
                ldsm_x4(bfr[p], baseB + (uint32_t)((warp_n * 32 + p * 16 + brow) * 80
                                                   + s * 32 + bcol));
            #pragma unroll
            for (int nt = 0; nt < 4; nt++) {
                uint32_t b0 = bfr[nt >> 1][(nt & 1) * 2 + 0];
                uint32_t b1 = bfr[nt >> 1][(nt & 1) * 2 + 1];
                #pragma unroll
                for (int mt = 0; mt < 4; mt++)
                    mma_bf16(acc[mt][nt], af[mt][0], af[mt][1], af[mt][2], af[mt][3],
                             b0, b1);
            }
        }
        __syncthreads();
    }

    // ---- epilogue ----
    int lr = lane >> 2;
    int lc = lane & 3;
    #pragma unroll
    for (int nt = 0; nt < 4; nt++) {
        int n = warp_n * 32 + nt * 8 + lc * 2;
        float2 bv = __ldg((const float2*)(bias + n));
        #pragma unroll
        for (int mt = 0; mt < 4; mt++) {
            #pragma unroll
            for (int h = 0; h < 2; h++) {
                int gm = m0 + warp_m * 64 + mt * 16 + lr + h * 8;
                if (gm >= M) continue;
                float v0 = acc[mt][nt][h * 2 + 0] + bv.x;
                float v1 = acc[mt][nt][h * 2 + 1] + bv.y;
                if (SINGLE) {
                    __nv_bfloat162 o = __float22bfloat162_rn(make_float2(v0, v1));
                    *(__nv_bfloat162*)(TS + (size_t)gm * 128 + n) = o;
                } else if (y < 2) {
                    __nv_bfloat162 o = __float22bfloat162_rn(make_float2(v0, v1));
                    *(__nv_bfloat162*)(TS + (size_t)gm * 256 + 2 * n + (y ? 2 : 0)) = o;
                } else {
                    float* P = (y == 2) ? U : R;
                    *(float2*)(P + (size_t)gm * 128 + n) = make_float2(v0, v1);
                }
            }
        }
    }
}

// ----------------------------------------------------------------------------
// Fused aggregation + cell epilogue: warp per destination node.
// off/U/R/H are pre-offset by the node-range base; TS and ssrc/scoef stay
// global (gathers use absolute indices).
// ----------------------------------------------------------------------------
__global__ __launch_bounds__(256)
void agg_epi_kernel(const int* __restrict__ off,
                    const int* __restrict__ ssrc,
                    const float2* __restrict__ scoef,
                    const __nv_bfloat16* __restrict__ TS,
                    const float* __restrict__ U,
                    const float* __restrict__ R,
                    __nv_bfloat16* __restrict__ H, int N) {
    int lane = threadIdx.x & 31;
    int w = (blockIdx.x * blockDim.x + threadIdx.x) >> 5;
    if (w >= N) return;
    int s0 = __ldg(off + w);
    int s1 = __ldg(off + w + 1);
    float a1x = 0.f, a1y = 0.f, a1z = 0.f, a1w = 0.f;
    float a2x = 0.f, a2y = 0.f, a2z = 0.f, a2w = 0.f;
    #pragma unroll 2
    for (int e = s0; e < s1; e++) {
        int sr = __ldg(ssrc + e);
        float2 c = __ldg(scoef + e);
        uint4 v = __ldg((const uint4*)(TS + (size_t)sr * 256) + lane);
        float2 t0 = __bfloat1622float2(*(__nv_bfloat162*)&v.x);
        float2 q0 = __bfloat1622float2(*(__nv_bfloat162*)&v.y);
        float2 t1 = __bfloat1622float2(*(__nv_bfloat162*)&v.z);
        float2 q1 = __bfloat1622float2(*(__nv_bfloat162*)&v.w);
        a1x += c.x * t0.x; a1y += c.x * t0.y; a1z += c.x * t1.x; a1w += c.x * t1.y;
        a2x += c.y * q0.x; a2y += c.y * q0.y; a2z += c.y * q1.x; a2w += c.y * q1.y;
    }
    size_t base = (size_t)w * 128 + lane * 4;
    float4 uv = __ldg((const float4*)(U + base));
    float4 rv = __ldg((const float4*)(R + base));
    float h1x = fmaxf(a1x + uv.x, 0.f);
    float h1y = fmaxf(a1y + uv.y, 0.f);
    float h1z = fmaxf(a1z + uv.z, 0.f);
    float h1w = fmaxf(a1w + uv.w, 0.f);
    float v, h2x, h2y, h2z, h2w;
    v = a2x + rv.x; h2x = (v > 0.f) ? v : expm1f(0.01f * v);
    v = a2y + rv.y; h2y = (v > 0.f) ? v : expm1f(0.01f * v);
    v = a2z + rv.z; h2z = (v > 0.f) ? v : expm1f(0.01f * v);
    v = a2w + rv.w; h2w = (v > 0.f) ? v : expm1f(0.01f * v);

    uint2 o1, o2;
    *(__nv_bfloat162*)&o1.x = __float22bfloat162_rn(make_float2(h1x, h1y));
    *(__nv_bfloat162*)&o1.y = __float22bfloat162_rn(make_float2(h1z, h1w));
    *(__nv_bfloat162*)&o2.x = __float22bfloat162_rn(make_float2(h2x, h2y));
    *(__nv_bfloat162*)&o2.y = __float22bfloat162_rn(make_float2(h2z, h2w));
    *(uint2*)(H + (size_t)w * 256 + lane * 4) = o1;
    *(uint2*)(H + (size_t)w * 256 + 128 + lane * 4) = o2;
}

// ----------------------------------------------------------------------------
// Classifier (bf16 input): logits = h @ cls_w + cls_b ; out = log_softmax
// h/out may be pre-offset by a node-range base.
// ----------------------------------------------------------------------------
__global__ __launch_bounds__(256)
void cls_kernel(const __nv_bfloat16* __restrict__ h, const float* __restrict__ W,
                const float* __restrict__ b, float* __restrict__ out, int M) {
    __shared__ float WsT[16 * 256];
    __shared__ float Bsm[16];
    int tid = threadIdx.x;
    for (int idx = tid; idx < 16 * 256; idx += 256) {
        int c = idx >> 8, k = idx & 255;
        WsT[c * 256 + k] = W[k * 16 + c];
    }
    if (tid < 16) Bsm[tid] = b[tid];
    __syncthreads();

    int warp = tid >> 5;
    int lane = tid & 31;
    for (int n = blockIdx.x * 8 + warp; n < M; n += gridDim.x * 8) {
        uint4 raw = __ldg((const uint4*)(h + (size_t)n * 256 + lane * 8));
        float hv[8];
        {
            float2 f0 = __bfloat1622float2(*(__nv_bfloat162*)&raw.x);
            float2 f1 = __bfloat1622float2(*(__nv_bfloat162*)&raw.y);
            float2 f2 = __bfloat1622float2(*(__nv_bfloat162*)&raw.z);
            float2 f3 = __bfloat1622float2(*(__nv_bfloat162*)&raw.w);
            hv[0] = f0.x; hv[1] = f0.y; hv[2] = f1.x; hv[3] = f1.y;
            hv[4] = f2.x; hv[5] = f2.y; hv[6] = f3.x; hv[7] = f3.y;
        }
        float acc[16];
        #pragma unroll
        for (int c = 0; c < 16; c++) {
            const float4* wp = (const float4*)&WsT[c * 256 + lane * 8];
            float4 w0 = wp[0];
            float4 w1 = wp[1];
            acc[c] = hv[0] * w0.x + hv[1] * w0.y + hv[2] * w0.z + hv[3] * w0.w
                   + hv[4] * w1.x + hv[5] * w1.y + hv[6] * w1.z + hv[7] * w1.w;
        }
        #pragma unroll
        for (int c = 0; c < 16; c++) {
            #pragma unroll
            for (int offs = 16; offs > 0; offs >>= 1)
                acc[c] += __shfl_xor_sync(0xFFFFFFFFu, acc[c], offs);
        }
        float l[16];
        float mx = -3.402823e38f;
        #pragma unroll
        for (int c = 0; c < 16; c++) { l[c] = acc[c] + Bsm[c]; mx = fmaxf(mx, l[c]); }
        float se = 0.f;
        #pragma unroll
        for (int c = 0; c < 16; c++) se += expf(l[c] - mx);
        float lse = mx + logf(se);
        if (lane < 16) out[(size_t)n * 16 + lane] = l[lane] - lse;
    }
}

// ----------------------------------------------------------------------------
// Launch — two-stream pipelined capture. The post-gemm0 serial chain
// (agg0 -> pre1 -> quad1 -> agg1 -> cls) is split into node-range halves
// running skewed on the two streams; quad1->agg1 is the only full barrier
// (cross-half gathers), handled with eQ1a/eQ1b.
// Static stream/events: lazy channel allocation lands on the uncaptured
// first call, before the pre-capture memory baseline.
// ----------------------------------------------------------------------------
static void* sym(const void* s) {
    void* p = nullptr;
    cudaGetSymbolAddress(&p, s);
    return p;
}

extern "C" void kernel_launch(void* const* d_in, const int* in_sizes, int n_in,
                              void* d_out, int out_size) {
    const float* x        = (const float*)d_in[0];
    const int*   ei       = (const int*)  d_in[1];
    const float* ew       = (const float*)d_in[2];
    const float* pre_w0   = (const float*)d_in[3];
    const float* pre_b0   = (const float*)d_in[4];
    const float* arma_w0  = (const float*)d_in[5];
    const float* arma_v0  = (const float*)d_in[6];
    const float* arma_b0  = (const float*)d_in[7];
    const float* sage_wl0 = (const float*)d_in[8];
    const float* sage_bl0 = (const float*)d_in[9];
    const float* sage_wr0 = (const float*)d_in[10];
    const float* pre_w1   = (const float*)d_in[11];
    const float* pre_b1   = (const float*)d_in[12];
    const float* arma_w1  = (const float*)d_in[13];
    const float* arma_v1  = (const float*)d_in[14];
    const float* arma_b1  = (const float*)d_in[15];
    const float* sage_wl1 = (const float*)d_in[16];
    const float* sage_bl1 = (const float*)d_in[17];
    const float* sage_wr1 = (const float*)d_in[18];
    const float* cls_w    = (const float*)d_in[19];
    const float* cls_b    = (const float*)d_in[20];
    float* out = (float*)d_out;

    const int* row = ei;
    const int* col = ei + EE;

    __nv_bfloat16* pxb   = (__nv_bfloat16*)sym(g_xb);
    __nv_bfloat16* phb   = (__nv_bfloat16*)sym(g_hb);
    __nv_bfloat16* phpre = (__nv_bfloat16*)sym(g_hpre);
    float*  pu    = (float*) sym(g_u);
    float*  pr    = (float*) sym(g_r);
    __nv_bfloat16* pts = (__nv_bfloat16*)sym(g_ts);
    float*  pdeg  = (float*) sym(g_deg);
    int*    pcnti = (int*)   sym(g_cnti);
    int*    pcur  = (int*)   sym(g_cur);
    int*    poff  = (int*)   sym(g_off);
    int*    pblk  = (int*)   sym(g_blksum);
    float*  pdinv = (float*) sym(g_dinv);
    float*  picnt = (float*) sym(g_icnt);
    int*    pssrc = (int*)   sym(g_ssrc);
    float2* pscoef= (float2*)sym(g_scoef);
    __nv_bfloat16* pWt = (__nv_bfloat16*)sym(g_Wt);
    __nv_bfloat16* pWs = (__nv_bfloat16*)sym(g_Ws);
    __nv_bfloat16* pWu = (__nv_bfloat16*)sym(g_Wu);
    __nv_bfloat16* pWr = (__nv_bfloat16*)sym(g_Wr);
    float* pbt = (float*)sym(g_bt); float* pbs = (float*)sym(g_bs);
    float* pbu = (float*)sym(g_bu); float* pbr = (float*)sym(g_br);
    __nv_bfloat16* pWp  = (__nv_bfloat16*)sym(g_Wp);
    __nv_bfloat16* pW1t = (__nv_bfloat16*)sym(g_W1t);
    __nv_bfloat16* pW1s = (__nv_bfloat16*)sym(g_W1s);
    __nv_bfloat16* pW1u = (__nv_bfloat16*)sym(g_W1u);
    __nv_bfloat16* pW1r = (__nv_bfloat16*)sym(g_W1r);
    float* pzero = (float*)sym(g_zero);

    const int M = NN;
    const int MB = (M + 127) / 128;
    const int MBa = H1N / 128;                 // 391
    const int MBb = (H2N + 127) / 128;         // 391
    const int agg_a = (H1N * 32 + 255) / 256;
    const int agg_b = (H2N * 32 + 255) / 256;
    const int n8 = NN * 128 / 8;

    struct Ctx {
        cudaStream_t s2;
        cudaEvent_t eFork, eCsr, eW1, eG0, eQ1a, eQ1b, eDone;
        Ctx() {
            cudaStreamCreateWithFlags(&s2, cudaStreamNonBlocking);
            cudaEventCreateWithFlags(&eFork, cudaEventDisableTiming);
            cudaEventCreateWithFlags(&eCsr,  cudaEventDisableTiming);
            cudaEventCreateWithFlags(&eW1,   cudaEventDisableTiming);
            cudaEventCreateWithFlags(&eG0,   cudaEventDisableTiming);
            cudaEventCreateWithFlags(&eQ1a,  cudaEventDisableTiming);
            cudaEventCreateWithFlags(&eQ1b,  cudaEventDisableTiming);
            cudaEventCreateWithFlags(&eDone, cudaEventDisableTiming);
        }
    };
    static Ctx ctx;
    cudaStream_t s2 = ctx.s2;

    cudaEventRecord(ctx.eFork, 0);

    // ---- main: cell-0 compose + x conversion + full quad GEMM ----
    compose_w_kernel<<<dim3(128 * 128 / 256, 4), 256>>>(        // idx 0
        pre_w0, 128, arma_w0, sage_wl0, arma_v0, sage_wr0, pWt, pWs, pWu, pWr);
    compose_b_kernel<<<1, 512>>>(pre_b0, arma_w0, sage_wl0,     // idx 1
                                 arma_v0, sage_wr0, arma_b0, sage_bl0,
                                 pbt, pbs, pbu, pbr);
    xcvt_kernel<<<(n8 + 255) / 256, 256>>>(x, pxb, n8);         // idx 2
    quad_gemm_kernel<0><<<dim3(MB, 4), 256>>>(                  // idx 3 <- profiled
        pxb, 128, pWt, pWs, pWu, pWr, pbt, pbs, pbu, pbr,
        pts, pu, pr, M, 128);
    cudaEventRecord(ctx.eG0, 0);

    // ---- side: cell-1 weight transposes, then CSR build ----
    cudaStreamWaitEvent(s2, ctx.eFork, 0);
    transpose_w_kernel<<<(256 * 128 + 255) / 256, 256, 0, s2>>>(pre_w1, pWp, 256);
    transpose_w_kernel<<<(128 * 128 + 255) / 256, 256, 0, s2>>>(arma_w1, pW1t, 128);
    transpose_w_kernel<<<(128 * 128 + 255) / 256, 256, 0, s2>>>(sage_wl1, pW1s, 128);
    transpose_w_kernel<<<(128 * 128 + 255) / 256, 256, 0, s2>>>(arma_v1, pW1u, 128);
    transpose_w_kernel<<<(128 * 128 + 255) / 256, 256, 0, s2>>>(sage_wr1, pW1r, 128);
    cudaEventRecord(ctx.eW1, s2);
    init_counts_kernel<<<(NN + 255) / 256, 256, 0, s2>>>(pdeg, pcnti, pcur, NN);
    hist_kernel<<<(EE + 255) / 256, 256, 0, s2>>>(col, ew, pdeg, pcnti, EE);
    dinv_kernel<<<(NN + 255) / 256, 256, 0, s2>>>(pdeg, pcnti, pdinv, picnt, NN);
    scan1_kernel<<<NBLK, SCAN_B, 0, s2>>>(pcnti, poff, pblk, NN);
    scan2_kernel<<<1, SCAN_B, 0, s2>>>(pblk, NBLK);
    scan3_kernel<<<(NN + 255) / 256, 256, 0, s2>>>(poff, pblk, NN, EE);
    edge_sort_kernel<<<(EE + 255) / 256, 256, 0, s2>>>(row, col, ew, poff, pcur,
                                                       pdinv, picnt, pssrc, pscoef, EE);
    cudaEventRecord(ctx.eCsr, s2);

    // ============ pipelined half-chains ============
    // main half-a: agg0_a -> pre1_a -> quad1_a
    cudaStreamWaitEvent(0, ctx.eCsr, 0);
    cudaStreamWaitEvent(0, ctx.eW1, 0);
    agg_epi_kernel<<<agg_a, 256>>>(poff, pssrc, pscoef, pts,
                                   pu, pr, phb, H1N);
    quad_gemm_kernel<1><<<dim3(MBa, 1), 256>>>(
        phb, 256, pWp, nullptr, nullptr, nullptr,
        pre_b1, nullptr, nullptr, nullptr,
        phpre, nullptr, nullptr, H1N, 256);
    quad_gemm_kernel<0><<<dim3(MBa, 4), 256>>>(
        phpre, 128, pW1t, pW1s, pW1u, pW1r,
        pzero, pzero, arma_b1, sage_bl1,
        pts, pu, pr, H1N, 128);
    cudaEventRecord(ctx.eQ1a, 0);

    // side half-b: agg0_b -> pre1_b -> quad1_b (needs gemm0; CSR on-stream)
    cudaStreamWaitEvent(s2, ctx.eG0, 0);
    agg_epi_kernel<<<agg_b, 256, 0, s2>>>(poff + H1N, pssrc, pscoef, pts,
                                          pu + (size_t)H1N * 128,
                                          pr + (size_t)H1N * 128,
                                          phb + (size_t)H1N * 256, H2N);
    quad_gemm_kernel<1><<<dim3(MBb, 1), 256, 0, s2>>>(
        phb + (size_t)H1N * 256, 256, pWp, nullptr, nullptr, nullptr,
        pre_b1, nullptr, nullptr, nullptr,
        phpre + (size_t)H1N * 128, nullptr, nullptr, H2N, 256);
    quad_gemm_kernel<0><<<dim3(MBb, 4), 256, 0, s2>>>(
        phpre + (size_t)H1N * 128, 128, pW1t, pW1s, pW1u, pW1r,
        pzero, pzero, arma_b1, sage_bl1,
        pts + (size_t)H1N * 256,
        pu + (size_t)H1N * 128,
        pr + (size_t)H1N * 128, H2N, 128);
    cudaEventRecord(ctx.eQ1b, s2);

    // agg1 halves (each needs BOTH quad1 halves: cross-half gathers)
    cudaStreamWaitEvent(0, ctx.eQ1b, 0);
    agg_epi_kernel<<<agg_a, 256>>>(poff, pssrc, pscoef, pts,
                                   pu, pr, phb, H1N);
    cls_kernel<<<(H1N + 7) / 8, 256>>>(phb, cls_w, cls_b, out, H1N);

    cudaStreamWaitEvent(s2, ctx.eQ1a, 0);
    agg_epi_kernel<<<agg_b, 256, 0, s2>>>(poff + H1N, pssrc, pscoef, pts,
                                          pu + (size_t)H1N * 128,
                                          pr + (size_t)H1N * 128,
                                          phb + (size_t)H1N * 256, H2N);
    cls_kernel<<<(H2N + 7) / 8, 256, 0, s2>>>(phb + (size_t)H1N * 256,
                                              cls_w, cls_b,
                                              out + (size_t)H1N * 16, H2N);
    cudaEventRecord(ctx.eDone, s2);

    // join side stream back into the origin stream
    cudaStreamWaitEvent(0, ctx.eDone, 0);
}

// round 17
// speedup vs baseline: 1.1888x; 1.1198x over previous
#include <cuda_runtime.h>
#include <cuda_bf16.h>
#include <math.h>
#include <stdint.h>

// Problem constants (fixed by the reference setup)
#define NN 100000
#define EE 1600000
#define SCAN_B 1024
#define NBLK ((NN + SCAN_B - 1) / SCAN_B)   // 98
#define H1N 50048                            // 391 * 128 (first half, block-aligned)
#define H2N (NN - H1N)                       // 49952

// ----------------------------------------------------------------------------
// Scratch (device globals; allocation inside kernel_launch is forbidden)
// ----------------------------------------------------------------------------
__device__ __nv_bfloat16 g_xb  [(size_t)NN * 128]; // x converted to bf16
__device__ __nv_bfloat16 g_hb  [(size_t)NN * 256]; // cell-0 output (bf16)
__device__ __nv_bfloat16 g_hpre[(size_t)NN * 128]; // cell-1 pre-linear (bf16)
__device__ float g_u [(size_t)NN * 128];
__device__ float g_r [(size_t)NN * 128];
// interleaved T|S rows: [t0,t1,s0,s1,...] 256 bf16 per node
__device__ __nv_bfloat16 g_ts[(size_t)NN * 256];
__device__ float  g_deg [NN];
__device__ int    g_cnti[NN];
__device__ int    g_cur [NN];
__device__ int    g_off [NN + 1];
__device__ int    g_blksum[SCAN_B];
__device__ float  g_dinv[NN];
__device__ float  g_icnt[NN];
__device__ int    g_ssrc[EE];
__device__ float2 g_scoef[EE];
// cell-0 composed weights bf16 TRANSPOSED [n][128]; biases fp32 [n]
__device__ __nv_bfloat16 g_Wt[128 * 128];
__device__ __nv_bfloat16 g_Ws[128 * 128];
__device__ __nv_bfloat16 g_Wu[128 * 128];
__device__ __nv_bfloat16 g_Wr[128 * 128];
__device__ float g_bt[128];
__device__ float g_bs[128];
__device__ float g_bu[128];
__device__ float g_br[128];
// cell-1 plain transposed weights (bf16)
__device__ __nv_bfloat16 g_Wp [128 * 256];  // pre_w1^T  [n][256]
__device__ __nv_bfloat16 g_W1t[128 * 128];  // arma_w1^T
__device__ __nv_bfloat16 g_W1s[128 * 128];  // sage_wl1^T
__device__ __nv_bfloat16 g_W1u[128 * 128];  // arma_v1^T
__device__ __nv_bfloat16 g_W1r[128 * 128];  // sage_wr1^T
__device__ float g_zero[128];               // zero-initialized, never written

// ----------------------------------------------------------------------------
// Small helpers
// ----------------------------------------------------------------------------
__device__ __forceinline__ uint32_t packbf(float a, float b) {
    __nv_bfloat162 h = __float22bfloat162_rn(make_float2(a, b));
    return *(uint32_t*)&h;
}

#define CP_ASYNC16(dst_u32, src_ptr) \
    asm volatile("cp.async.cg.shared.global [%0], [%1], 16;" \
                 :: "r"(dst_u32), "l"(src_ptr) : "memory")
#define CP_COMMIT() asm volatile("cp.async.commit_group;" ::: "memory")
#define CP_WAIT1()  asm volatile("cp.async.wait_group 1;" ::: "memory")
#define CP_WAIT0()  asm volatile("cp.async.wait_group 0;" ::: "memory")

__device__ __forceinline__ void ldsm_x4(uint32_t r[4], uint32_t saddr) {
    asm volatile("ldmatrix.sync.aligned.m8n8.x4.shared.b16 {%0,%1,%2,%3}, [%4];"
        : "=r"(r[0]), "=r"(r[1]), "=r"(r[2]), "=r"(r[3]) : "r"(saddr));
}

__device__ __forceinline__ void mma_bf16(float c[4], uint32_t a0, uint32_t a1,
                                         uint32_t a2, uint32_t a3,
                                         uint32_t b0, uint32_t b1) {
    asm volatile(
        "mma.sync.aligned.m16n8k16.row.col.f32.bf16.bf16.f32 "
        "{%0,%1,%2,%3}, {%4,%5,%6,%7}, {%8,%9}, {%0,%1,%2,%3};"
        : "+f"(c[0]), "+f"(c[1]), "+f"(c[2]), "+f"(c[3])
        : "r"(a0), "r"(a1), "r"(a2), "r"(a3), "r"(b0), "r"(b1));
}

// ----------------------------------------------------------------------------
// x -> bf16 conversion
// ----------------------------------------------------------------------------
__global__ void xcvt_kernel(const float* __restrict__ x,
                            __nv_bfloat16* __restrict__ xb, int n8) {
    int i = blockIdx.x * blockDim.x + threadIdx.x;
    if (i >= n8) return;
    const float4* p = (const float4*)(x + (size_t)i * 8);
    float4 v0 = p[0], v1 = p[1];
    uint4 u;
    u.x = packbf(v0.x, v0.y);
    u.y = packbf(v0.z, v0.w);
    u.z = packbf(v1.x, v1.y);
    u.w = packbf(v1.z, v1.w);
    *(uint4*)(xb + (size_t)i * 8) = u;
}

// ----------------------------------------------------------------------------
// Weight transpose: in fp32 [K][128] -> out bf16 [128][K]
// ----------------------------------------------------------------------------
__global__ void transpose_w_kernel(const float* __restrict__ in,
                                   __nv_bfloat16* __restrict__ out, int K) {
    int idx = blockIdx.x * blockDim.x + threadIdx.x;
    if (idx >= K * 128) return;
    int k = idx >> 7;
    int n = idx & 127;
    out[(size_t)n * K + k] = __float2bfloat16(in[idx]);
}

// ----------------------------------------------------------------------------
// CSR build
// ----------------------------------------------------------------------------
__global__ void init_counts_kernel(float* __restrict__ deg, int* __restrict__ cnt,
                                   int* __restrict__ cur, int n) {
    int i = blockIdx.x * blockDim.x + threadIdx.x;
    if (i < n) { deg[i] = 0.f; cnt[i] = 0; cur[i] = 0; }
}

__global__ void hist_kernel(const int* __restrict__ col,
                            const float* __restrict__ ew,
                            float* __restrict__ deg, int* __restrict__ cnt, int E) {
    int e = blockIdx.x * blockDim.x + threadIdx.x;
    if (e >= E) return;
    int c = col[e];
    atomicAdd(&deg[c], ew[e]);
    atomicAdd(&cnt[c], 1);
}

__global__ void dinv_kernel(const float* __restrict__ deg,
                            const int* __restrict__ cnt,
                            float* __restrict__ dinv,
                            float* __restrict__ icnt, int n) {
    int i = blockIdx.x * blockDim.x + threadIdx.x;
    if (i >= n) return;
    float d = deg[i];
    dinv[i] = (d > 0.f) ? rsqrtf(d) : 0.f;
    icnt[i] = 1.0f / fmaxf((float)cnt[i], 1.0f);
}

__global__ void scan1_kernel(const int* __restrict__ cnt, int* __restrict__ off,
                             int* __restrict__ blksum, int n) {
    __shared__ int sh[SCAN_B];
    int t = threadIdx.x;
    int i = blockIdx.x * SCAN_B + t;
    int v = (i < n) ? cnt[i] : 0;
    sh[t] = v;
    __syncthreads();
    for (int o = 1; o < SCAN_B; o <<= 1) {
        int x = (t >= o) ? sh[t - o] : 0;
        __syncthreads();
        sh[t] += x;
        __syncthreads();
    }
    if (i < n) off[i] = sh[t] - v;          // exclusive
    if (t == SCAN_B - 1) blksum[blockIdx.x] = sh[t];
}

__global__ void scan2_kernel(int* __restrict__ blksum, int nb) {
    __shared__ int sh[SCAN_B];
    int t = threadIdx.x;
    int v = (t < nb) ? blksum[t] : 0;
    sh[t] = v;
    __syncthreads();
    for (int o = 1; o < SCAN_B; o <<= 1) {
        int x = (t >= o) ? sh[t - o] : 0;
        __syncthreads();
        sh[t] += x;
        __syncthreads();
    }
    if (t < nb) blksum[t] = sh[t] - v;
}

__global__ void scan3_kernel(int* __restrict__ off, const int* __restrict__ blksum,
                             int n, int E) {
    int i = blockIdx.x * blockDim.x + threadIdx.x;
    if (i < n) off[i] += blksum[i / SCAN_B];
    if (i == 0) off[n] = E;
}

__global__ void edge_sort_kernel(const int* __restrict__ row,
                                 const int* __restrict__ col,
                                 const float* __restrict__ ew,
                                 const int* __restrict__ off,
                                 int* __restrict__ cur,
                                 const float* __restrict__ dinv,
                                 const float* __restrict__ icnt,
                                 int* __restrict__ ssrc,
                                 float2* __restrict__ scoef, int E) {
    int e = blockIdx.x * blockDim.x + threadIdx.x;
    if (e >= E) return;
    int c = col[e];
    int r = row[e];
    float w = ew[e];
    int p = off[c] + atomicAdd(&cur[c], 1);
    ssrc[p] = r;
    scoef[p] = make_float2(dinv[r] * w * dinv[c], w * icnt[c]);
}

// ----------------------------------------------------------------------------
// Cell-0 weight composition, bf16 transposed: O[n][k] = sum_j pre_w[k][j]*X[j][n]
// ----------------------------------------------------------------------------
__global__ void compose_w_kernel(const float* __restrict__ pre_w, int K,
                                 const float* __restrict__ X0,
                                 const float* __restrict__ X1,
                                 const float* __restrict__ X2,
                                 const float* __restrict__ X3,
                                 __nv_bfloat16* __restrict__ O0,
                                 __nv_bfloat16* __restrict__ O1,
                                 __nv_bfloat16* __restrict__ O2,
                                 __nv_bfloat16* __restrict__ O3) {
    int idx = blockIdx.x * blockDim.x + threadIdx.x;
    if (idx >= K * 128) return;
    int k = idx >> 7;
    int n = idx & 127;
    const float* X = X0;
    __nv_bfloat16* O = O0;
    if (blockIdx.y == 1) { X = X1; O = O1; }
    else if (blockIdx.y == 2) { X = X2; O = O2; }
    else if (blockIdx.y == 3) { X = X3; O = O3; }
    float acc = 0.f;
    const float* pw = pre_w + (size_t)k * 128;
    #pragma unroll 8
    for (int j = 0; j < 128; j++)
        acc += pw[j] * __ldg(X + (size_t)j * 128 + n);
    O[(size_t)n * K + k] = __float2bfloat16(acc);
}

__global__ void compose_b_kernel(const float* __restrict__ pre_b,
                                 const float* __restrict__ X0,
                                 const float* __restrict__ X1,
                                 const float* __restrict__ X2,
                                 const float* __restrict__ X3,
                                 const float* __restrict__ e2,
                                 const float* __restrict__ e3,
                                 float* __restrict__ O0, float* __restrict__ O1,
                                 float* __restrict__ O2, float* __restrict__ O3) {
    int tid = threadIdx.x;           // 512 threads: y = tid/128, n = tid%128
    int y = tid >> 7;
    int n = tid & 127;
    const float* X = (y == 0) ? X0 : (y == 1) ? X1 : (y == 2) ? X2 : X3;
    float acc = 0.f;
    #pragma unroll 8
    for (int j = 0; j < 128; j++)
        acc += pre_b[j] * __ldg(X + (size_t)j * 128 + n);
    if (y == 2) acc += e2[n];
    if (y == 3) acc += e3[n];
    float* O = (y == 0) ? O0 : (y == 1) ? O1 : (y == 2) ? O2 : O3;
    O[n] = acc;
}

// ----------------------------------------------------------------------------
// BF16 mma.sync GEMM (m16n8k16), BK=32, cp.async double-buffered, ldmatrix.x4.
// SINGLE=0 (quad): grid (MB,4). y=0: t -> TS interleaved; y=1: s -> TS
//   interleaved (+2 bf16 offset); y=2: U fp32; y=3: R fp32.
// SINGLE=1: one output, bf16 plain rows [gm][128] into TS.
// All pointers may be pre-offset by a node-range base; M is the range size.
// ----------------------------------------------------------------------------
#define ROW_U32 20          // 16 u32 data (32 bf16) + 4 pad
#define BUF_B   (128 * ROW_U32 * 4)   // 10240 bytes per tile buffer

template<int SINGLE>
__global__ __launch_bounds__(256, 2)
void quad_gemm_kernel(const __nv_bfloat16* __restrict__ A, int lda,
                      const __nv_bfloat16* __restrict__ Wt,
                      const __nv_bfloat16* __restrict__ Ws,
                      const __nv_bfloat16* __restrict__ Wu,
                      const __nv_bfloat16* __restrict__ Wr,
                      const float* __restrict__ bt, const float* __restrict__ bs,
                      const float* __restrict__ bu, const float* __restrict__ br,
                      __nv_bfloat16* __restrict__ TS,
                      float* __restrict__ U, float* __restrict__ R,
                      int M, int K) {
    __shared__ uint32_t smem[2 * 2 * 128 * ROW_U32];   // 40960 bytes

    int tid = threadIdx.x;
    int lane = tid & 31;
    int wid = tid >> 5;
    int warp_m = wid & 1;
    int warp_n = wid >> 1;
    int m0 = blockIdx.x * 128;
    int y = SINGLE ? 0 : blockIdx.y;

    const __nv_bfloat16* W = (y == 0) ? Wt : (y == 1) ? Ws : (y == 2) ? Wu : Wr;
    const float* bias = (y == 0) ? bt : (y == 1) ? bs : (y == 2) ? bu : br;

    uint32_t sb = (uint32_t)__cvta_generic_to_shared(smem);

    float acc[4][4][4];
    #pragma unroll
    for (int mt = 0; mt < 4; mt++)
        #pragma unroll
        for (int nt = 0; nt < 4; nt++)
            #pragma unroll
            for (int q = 0; q < 4; q++) acc[mt][nt][q] = 0.f;

    int arow = (lane & 7) + (((lane >> 3) & 1) << 3);
    int acol = (((lane >> 4) & 1) << 4);
    int brow = (lane & 7) + (((lane >> 4) & 1) << 3);
    int bcol = (((lane >> 3) & 1) << 4);

    int srow = tid >> 2;
    int sc4  = tid & 3;

    int nch = K >> 5;

    // prologue: stage chunk 0 into buffers 0
    {
        #pragma unroll
        for (int it = 0; it < 2; it++) {
            int r0 = srow + it * 64;
            int gm = m0 + r0;
            uint32_t dA = sb + (uint32_t)(r0 * 80 + sc4 * 16);
            if (gm < M) {
                CP_ASYNC16(dA, A + (size_t)gm * lda + sc4 * 8);
            } else {
                *(uint4*)((char*)smem + r0 * 80 + sc4 * 16) = make_uint4(0, 0, 0, 0);
            }
            uint32_t dB = sb + (uint32_t)(BUF_B + r0 * 80 + sc4 * 16);
            CP_ASYNC16(dB, W + (size_t)r0 * K + sc4 * 8);
        }
        CP_COMMIT();
    }

    for (int c = 0; c < nch; c++) {
        if (c + 1 < nch) {
            int st = (c + 1) & 1;
            int k0 = (c + 1) << 5;
            char* base = (char*)smem + st * 2 * BUF_B;
            uint32_t sbase = sb + (uint32_t)(st * 2 * BUF_B);
            #pragma unroll
            for (int it = 0; it < 2; it++) {
                int r0 = srow + it * 64;
                int gm = m0 + r0;
                uint32_t dA = sbase + (uint32_t)(r0 * 80 + sc4 * 16);
                if (gm < M) {
                    CP_ASYNC16(dA, A + (size_t)gm * lda + k0 + sc4 * 8);
                } else {
                    *(uint4*)(base + r0 * 80 + sc4 * 16) = make_uint4(0, 0, 0, 0);
                }
                uint32_t dB = sbase + (uint32_t)(BUF_B + r0 * 80 + sc4 * 16);
                CP_ASYNC16(dB, W + (size_t)r0 * K + k0 + sc4 * 8);
            }
            CP_COMMIT();
            CP_WAIT1();
        } else {
            CP_WAIT0();
        }
        __syncthreads();

        uint32_t baseA = sb + (uint32_t)((c & 1) * 2 * BUF_B);
        uint32_t baseB = baseA + BUF_B;
        #pragma unroll
        for (int s = 0; s < 2; s++) {
            uint32_t af[4][4];
            #pragma unroll
            for (int mt = 0; mt < 4; mt++)
                ldsm_x4(af[mt], baseA + (uint32_t)((warp_m * 64 + mt * 16 + arow) * 80
                                                   + s * 32 + acol));
            uint32_t bfr[2][4];
            #pragma unroll
            for (int p = 0; p < 2; p++)
                ldsm_x4(bfr[p], baseB + (uint32_t)((warp_n * 32 + p * 16 + brow) * 80
                                                   + s * 32 + bcol));
            #pragma unroll
            for (int nt = 0; nt < 4; nt++) {
                uint32_t b0 = bfr[nt >> 1][(nt & 1) * 2 + 0];
                uint32_t b1 = bfr[nt >> 1][(nt & 1) * 2 + 1];
                #pragma unroll
                for (int mt = 0; mt < 4; mt++)
                    mma_bf16(acc[mt][nt], af[mt][0], af[mt][1], af[mt][2], af[mt][3],
                             b0, b1);
            }
        }
        __syncthreads();
    }

    // ---- epilogue ----
    int lr = lane >> 2;
    int lc = lane & 3;
    #pragma unroll
    for (int nt = 0; nt < 4; nt++) {
        int n = warp_n * 32 + nt * 8 + lc * 2;
        float2 bv = __ldg((const float2*)(bias + n));
        #pragma unroll
        for (int mt = 0; mt < 4; mt++) {
            #pragma unroll
            for (int h = 0; h < 2; h++) {
                int gm = m0 + warp_m * 64 + mt * 16 + lr + h * 8;
                if (gm >= M) continue;
                float v0 = acc[mt][nt][h * 2 + 0] + bv.x;
                float v1 = acc[mt][nt][h * 2 + 1] + bv.y;
                if (SINGLE) {
                    __nv_bfloat162 o = __float22bfloat162_rn(make_float2(v0, v1));
                    *(__nv_bfloat162*)(TS + (size_t)gm * 128 + n) = o;
                } else if (y < 2) {
                    __nv_bfloat162 o = __float22bfloat162_rn(make_float2(v0, v1));
                    *(__nv_bfloat162*)(TS + (size_t)gm * 256 + 2 * n + (y ? 2 : 0)) = o;
                } else {
                    float* P = (y == 2) ? U : R;
                    *(float2*)(P + (size_t)gm * 128 + n) = make_float2(v0, v1);
                }
            }
        }
    }
}

// ----------------------------------------------------------------------------
// Fused aggregation + cell epilogue: warp per destination node.
// FINAL=0: write h (bf16, 256-wide) — cell-0 path.
// FINAL=1: fused classifier — compute h in-register (bf16-rounded, matching
//   the stored-h numerics), then logits = h@cls_w + cls_b, log_softmax -> out.
// off/U/R/H/out pre-offset by node-range base; TS/ssrc/scoef global.
// ----------------------------------------------------------------------------
template<int FINAL>
__global__ __launch_bounds__(256)
void agg_epi_kernel(const int* __restrict__ off,
                    const int* __restrict__ ssrc,
                    const float2* __restrict__ scoef,
                    const __nv_bfloat16* __restrict__ TS,
                    const float* __restrict__ U,
                    const float* __restrict__ R,
                    __nv_bfloat16* __restrict__ H,
                    const float* __restrict__ clsW,
                    const float* __restrict__ clsB,
                    float* __restrict__ out, int N) {
    __shared__ float WsT[FINAL ? 16 * 256 : 1];
    __shared__ float Bsm[FINAL ? 16 : 1];
    int tid = threadIdx.x;
    if (FINAL) {
        for (int idx = tid; idx < 16 * 256; idx += 256) {
            int c = idx >> 8, k = idx & 255;
            WsT[c * 256 + k] = clsW[k * 16 + c];
        }
        if (tid < 16) Bsm[tid] = clsB[tid];
        __syncthreads();
    }

    int lane = tid & 31;
    int w = (blockIdx.x * blockDim.x + tid) >> 5;
    if (w >= N) return;
    int s0 = __ldg(off + w);
    int s1 = __ldg(off + w + 1);
    float a1x = 0.f, a1y = 0.f, a1z = 0.f, a1w = 0.f;
    float a2x = 0.f, a2y = 0.f, a2z = 0.f, a2w = 0.f;
    #pragma unroll 2
    for (int e = s0; e < s1; e++) {
        int sr = __ldg(ssrc + e);
        float2 c = __ldg(scoef + e);
        uint4 v = __ldg((const uint4*)(TS + (size_t)sr * 256) + lane);
        float2 t0 = __bfloat1622float2(*(__nv_bfloat162*)&v.x);
        float2 q0 = __bfloat1622float2(*(__nv_bfloat162*)&v.y);
        float2 t1 = __bfloat1622float2(*(__nv_bfloat162*)&v.z);
        float2 q1 = __bfloat1622float2(*(__nv_bfloat162*)&v.w);
        a1x += c.x * t0.x; a1y += c.x * t0.y; a1z += c.x * t1.x; a1w += c.x * t1.y;
        a2x += c.y * q0.x; a2y += c.y * q0.y; a2z += c.y * q1.x; a2w += c.y * q1.y;
    }
    size_t base = (size_t)w * 128 + lane * 4;
    float4 uv = __ldg((const float4*)(U + base));
    float4 rv = __ldg((const float4*)(R + base));
    float h1x = fmaxf(a1x + uv.x, 0.f);
    float h1y = fmaxf(a1y + uv.y, 0.f);
    float h1z = fmaxf(a1z + uv.z, 0.f);
    float h1w = fmaxf(a1w + uv.w, 0.f);
    float v, h2x, h2y, h2z, h2w;
    v = a2x + rv.x; h2x = (v > 0.f) ? v : expm1f(0.01f * v);
    v = a2y + rv.y; h2y = (v > 0.f) ? v : expm1f(0.01f * v);
    v = a2z + rv.z; h2z = (v > 0.f) ? v : expm1f(0.01f * v);
    v = a2w + rv.w; h2w = (v > 0.f) ? v : expm1f(0.01f * v);

    // bf16 rounding (numerics identical to storing h as bf16 and re-reading)
    uint2 o1, o2;
    *(__nv_bfloat162*)&o1.x = __float22bfloat162_rn(make_float2(h1x, h1y));
    *(__nv_bfloat162*)&o1.y = __float22bfloat162_rn(make_float2(h1z, h1w));
    *(__nv_bfloat162*)&o2.x = __float22bfloat162_rn(make_float2(h2x, h2y));
    *(__nv_bfloat162*)&o2.y = __float22bfloat162_rn(make_float2(h2z, h2w));

    if (!FINAL) {
        *(uint2*)(H + (size_t)w * 256 + lane * 4) = o1;
        *(uint2*)(H + (size_t)w * 256 + 128 + lane * 4) = o2;
    } else {
        // unpack rounded values
        float hv[8];
        {
            float2 f0 = __bfloat1622float2(*(__nv_bfloat162*)&o1.x);
            float2 f1 = __bfloat1622float2(*(__nv_bfloat162*)&o1.y);
            float2 f2 = __bfloat1622float2(*(__nv_bfloat162*)&o2.x);
            float2 f3 = __bfloat1622float2(*(__nv_bfloat162*)&o2.y);
            hv[0] = f0.x; hv[1] = f0.y; hv[2] = f1.x; hv[3] = f1.y;
            hv[4] = f2.x; hv[5] = f2.y; hv[6] = f3.x; hv[7] = f3.y;
        }
        // features: h1 at cols lane*4..+3 ; h2 at 128+lane*4..+3
        int f0 = lane * 4;
        float acc[16];
        #pragma unroll
        for (int c = 0; c < 16; c++) {
            const float4* wp0 = (const float4*)&WsT[c * 256 + f0];
            const float4* wp1 = (const float4*)&WsT[c * 256 + 128 + f0];
            float4 w0 = wp0[0];
            float4 w1 = wp1[0];
            acc[c] = hv[0] * w0.x + hv[1] * w0.y + hv[2] * w0.z + hv[3] * w0.w
                   + hv[4] * w1.x + hv[5] * w1.y + hv[6] * w1.z + hv[7] * w1.w;
        }
        #pragma unroll
        for (int c = 0; c < 16; c++) {
            #pragma unroll
            for (int offs = 16; offs > 0; offs >>= 1)
                acc[c] += __shfl_xor_sync(0xFFFFFFFFu, acc[c], offs);
        }
        float l[16];
        float mx = -3.402823e38f;
        #pragma unroll
        for (int c = 0; c < 16; c++) { l[c] = acc[c] + Bsm[c]; mx = fmaxf(mx, l[c]); }
        float se = 0.f;
        #pragma unroll
        for (int c = 0; c < 16; c++) se += expf(l[c] - mx);
        float lse = mx + logf(se);
        if (lane < 16) out[(size_t)w * 16 + lane] = l[lane] - lse;
    }
}

// ----------------------------------------------------------------------------
// Launch — two-stream pipelined capture (R16 structure) with agg1+cls fused.
// Static stream/events: lazy channel allocation lands on the uncaptured
// first call, before the pre-capture memory baseline.
// ----------------------------------------------------------------------------
static void* sym(const void* s) {
    void* p = nullptr;
    cudaGetSymbolAddress(&p, s);
    return p;
}

extern "C" void kernel_launch(void* const* d_in, const int* in_sizes, int n_in,
                              void* d_out, int out_size) {
    const float* x        = (const float*)d_in[0];
    const int*   ei       = (const int*)  d_in[1];
    const float* ew       = (const float*)d_in[2];
    const float* pre_w0   = (const float*)d_in[3];
    const float* pre_b0   = (const float*)d_in[4];
    const float* arma_w0  = (const float*)d_in[5];
    const float* arma_v0  = (const float*)d_in[6];
    const float* arma_b0  = (const float*)d_in[7];
    const float* sage_wl0 = (const float*)d_in[8];
    const float* sage_bl0 = (const float*)d_in[9];
    const float* sage_wr0 = (const float*)d_in[10];
    const float* pre_w1   = (const float*)d_in[11];
    const float* pre_b1   = (const float*)d_in[12];
    const float* arma_w1  = (const float*)d_in[13];
    const float* arma_v1  = (const float*)d_in[14];
    const float* arma_b1  = (const float*)d_in[15];
    const float* sage_wl1 = (const float*)d_in[16];
    const float* sage_bl1 = (const float*)d_in[17];
    const float* sage_wr1 = (const float*)d_in[18];
    const float* cls_w    = (const float*)d_in[19];
    const float* cls_b    = (const float*)d_in[20];
    float* out = (float*)d_out;

    const int* row = ei;
    const int* col = ei + EE;

    __nv_bfloat16* pxb   = (__nv_bfloat16*)sym(g_xb);
    __nv_bfloat16* phb   = (__nv_bfloat16*)sym(g_hb);
    __nv_bfloat16* phpre = (__nv_bfloat16*)sym(g_hpre);
    float*  pu    = (float*) sym(g_u);
    float*  pr    = (float*) sym(g_r);
    __nv_bfloat16* pts = (__nv_bfloat16*)sym(g_ts);
    float*  pdeg  = (float*) sym(g_deg);
    int*    pcnti = (int*)   sym(g_cnti);
    int*    pcur  = (int*)   sym(g_cur);
    int*    poff  = (int*)   sym(g_off);
    int*    pblk  = (int*)   sym(g_blksum);
    float*  pdinv = (float*) sym(g_dinv);
    float*  picnt = (float*) sym(g_icnt);
    int*    pssrc = (int*)   sym(g_ssrc);
    float2* pscoef= (float2*)sym(g_scoef);
    __nv_bfloat16* pWt = (__nv_bfloat16*)sym(g_Wt);
    __nv_bfloat16* pWs = (__nv_bfloat16*)sym(g_Ws);
    __nv_bfloat16* pWu = (__nv_bfloat16*)sym(g_Wu);
    __nv_bfloat16* pWr = (__nv_bfloat16*)sym(g_Wr);
    float* pbt = (float*)sym(g_bt); float* pbs = (float*)sym(g_bs);
    float* pbu = (float*)sym(g_bu); float* pbr = (float*)sym(g_br);
    __nv_bfloat16* pWp  = (__nv_bfloat16*)sym(g_Wp);
    __nv_bfloat16* pW1t = (__nv_bfloat16*)sym(g_W1t);
    __nv_bfloat16* pW1s = (__nv_bfloat16*)sym(g_W1s);
    __nv_bfloat16* pW1u = (__nv_bfloat16*)sym(g_W1u);
    __nv_bfloat16* pW1r = (__nv_bfloat16*)sym(g_W1r);
    float* pzero = (float*)sym(g_zero);

    const int M = NN;
    const int MB = (M + 127) / 128;
    const int MBa = H1N / 128;                 // 391
    const int MBb = (H2N + 127) / 128;         // 391
    const int agg_a = (H1N * 32 + 255) / 256;
    const int agg_b = (H2N * 32 + 255) / 256;
    const int n8 = NN * 128 / 8;

    struct Ctx {
        cudaStream_t s2;
        cudaEvent_t eFork, eCsr, eW1, eG0, eQ1a, eQ1b, eDone;
        Ctx() {
            cudaStreamCreateWithFlags(&s2, cudaStreamNonBlocking);
            cudaEventCreateWithFlags(&eFork, cudaEventDisableTiming);
            cudaEventCreateWithFlags(&eCsr,  cudaEventDisableTiming);
            cudaEventCreateWithFlags(&eW1,   cudaEventDisableTiming);
            cudaEventCreateWithFlags(&eG0,   cudaEventDisableTiming);
            cudaEventCreateWithFlags(&eQ1a,  cudaEventDisableTiming);
            cudaEventCreateWithFlags(&eQ1b,  cudaEventDisableTiming);
            cudaEventCreateWithFlags(&eDone, cudaEventDisableTiming);
        }
    };
    static Ctx ctx;
    cudaStream_t s2 = ctx.s2;

    cudaEventRecord(ctx.eFork, 0);

    // ---- main: cell-0 compose + x conversion + full quad GEMM ----
    compose_w_kernel<<<dim3(128 * 128 / 256, 4), 256>>>(        // idx 0
        pre_w0, 128, arma_w0, sage_wl0, arma_v0, sage_wr0, pWt, pWs, pWu, pWr);
    compose_b_kernel<<<1, 512>>>(pre_b0, arma_w0, sage_wl0,     // idx 1
                                 arma_v0, sage_wr0, arma_b0, sage_bl0,
                                 pbt, pbs, pbu, pbr);
    xcvt_kernel<<<(n8 + 255) / 256, 256>>>(x, pxb, n8);         // idx 2
    quad_gemm_kernel<0><<<dim3(MB, 4), 256>>>(                  // idx 3 <- profiled
        pxb, 128, pWt, pWs, pWu, pWr, pbt, pbs, pbu, pbr,
        pts, pu, pr, M, 128);
    cudaEventRecord(ctx.eG0, 0);

    // ---- side: cell-1 weight transposes, then CSR build ----
    cudaStreamWaitEvent(s2, ctx.eFork, 0);
    transpose_w_kernel<<<(256 * 128 + 255) / 256, 256, 0, s2>>>(pre_w1, pWp, 256);
    transpose_w_kernel<<<(128 * 128 + 255) / 256, 256, 0, s2>>>(arma_w1, pW1t, 128);
    transpose_w_kernel<<<(128 * 128 + 255) / 256, 256, 0, s2>>>(sage_wl1, pW1s, 128);
    transpose_w_kernel<<<(128 * 128 + 255) / 256, 256, 0, s2>>>(arma_v1, pW1u, 128);
    transpose_w_kernel<<<(128 * 128 + 255) / 256, 256, 0, s2>>>(sage_wr1, pW1r, 128);
    cudaEventRecord(ctx.eW1, s2);
    init_counts_kernel<<<(NN + 255) / 256, 256, 0, s2>>>(pdeg, pcnti, pcur, NN);
    hist_kernel<<<(EE + 255) / 256, 256, 0, s2>>>(col, ew, pdeg, pcnti, EE);
    dinv_kernel<<<(NN + 255) / 256, 256, 0, s2>>>(pdeg, pcnti, pdinv, picnt, NN);
    scan1_kernel<<<NBLK, SCAN_B, 0, s2>>>(pcnti, poff, pblk, NN);
    scan2_kernel<<<1, SCAN_B, 0, s2>>>(pblk, NBLK);
    scan3_kernel<<<(NN + 255) / 256, 256, 0, s2>>>(poff, pblk, NN, EE);
    edge_sort_kernel<<<(EE + 255) / 256, 256, 0, s2>>>(row, col, ew, poff, pcur,
                                                       pdinv, picnt, pssrc, pscoef, EE);
    cudaEventRecord(ctx.eCsr, s2);

    // ============ pipelined half-chains ============
    // main half-a: agg0_a -> pre1_a -> quad1_a
    cudaStreamWaitEvent(0, ctx.eCsr, 0);
    cudaStreamWaitEvent(0, ctx.eW1, 0);
    agg_epi_kernel<0><<<agg_a, 256>>>(poff, pssrc, pscoef, pts,
                                      pu, pr, phb, nullptr, nullptr, nullptr, H1N);
    quad_gemm_kernel<1><<<dim3(MBa, 1), 256>>>(
        phb, 256, pWp, nullptr, nullptr, nullptr,
        pre_b1, nullptr, nullptr, nullptr,
        phpre, nullptr, nullptr, H1N, 256);
    quad_gemm_kernel<0><<<dim3(MBa, 4), 256>>>(
        phpre, 128, pW1t, pW1s, pW1u, pW1r,
        pzero, pzero, arma_b1, sage_bl1,
        pts, pu, pr, H1N, 128);
    cudaEventRecord(ctx.eQ1a, 0);

    // side half-b: agg0_b -> pre1_b -> quad1_b (needs gemm0; CSR on-stream)
    cudaStreamWaitEvent(s2, ctx.eG0, 0);
    agg_epi_kernel<0><<<agg_b, 256, 0, s2>>>(poff + H1N, pssrc, pscoef, pts,
                                             pu + (size_t)H1N * 128,
                                             pr + (size_t)H1N * 128,
                                             phb + (size_t)H1N * 256,
                                             nullptr, nullptr, nullptr, H2N);
    quad_gemm_kernel<1><<<dim3(MBb, 1), 256, 0, s2>>>(
        phb + (size_t)H1N * 256, 256, pWp, nullptr, nullptr, nullptr,
        pre_b1, nullptr, nullptr, nullptr,
        phpre + (size_t)H1N * 128, nullptr, nullptr, H2N, 256);
    quad_gemm_kernel<0><<<dim3(MBb, 4), 256, 0, s2>>>(
        phpre + (size_t)H1N * 128, 128, pW1t, pW1s, pW1u, pW1r,
        pzero, pzero, arma_b1, sage_bl1,
        pts + (size_t)H1N * 256,
        pu + (size_t)H1N * 128,
        pr + (size_t)H1N * 128, H2N, 128);
    cudaEventRecord(ctx.eQ1b, s2);

    // fused agg1+cls halves (each needs BOTH quad1 halves: cross-half gathers)
    cudaStreamWaitEvent(0, ctx.eQ1b, 0);
    agg_epi_kernel<1><<<agg_a, 256>>>(poff, pssrc, pscoef, pts,
                                      pu, pr, nullptr, cls_w, cls_b, out, H1N);

    cudaStreamWaitEvent(s2, ctx.eQ1a, 0);
    agg_epi_kernel<1><<<agg_b, 256, 0, s2>>>(poff + H1N, pssrc, pscoef, pts,
                                             pu + (size_t)H1N * 128,
                                             pr + (size_t)H1N * 128,
                                             nullptr, cls_w, cls_b,
                                             out + (size_t)H1N * 16, H2N);
    cudaEventRecord(ctx.eDone, s2);

    // join side stream back into the origin stream
    cudaStreamWaitEvent(0, ctx.eDone, 0);
}